// round 1
// baseline (speedup 1.0000x reference)
#include <cuda_runtime.h>
#include <math.h>

#define TT 512
#define BB 256
#define HH 128
#define XD 257
#define ZD 16
#define GG 512         // 4*H
#define RB 4           // batch rows per recurrent block
#define NBLK (BB/RB)   // 64 recurrent blocks
#define XROWS (BB*XD)  // 65792

// ---------------- scratch (device globals: sanctioned scratch path) ----------------
__device__ float d_xT[(size_t)TT*BB*XD];      // (t,b,257)
__device__ float d_gates[(size_t)TT*BB*GG];   // precomputed input gates for bwd LSTM
__device__ float d_gx[(size_t)TT*BB*HH];      // backward LSTM hidden states (t,b,128)
__device__ float d_u0[(size_t)TT*BB*HH];      // gx @ W0_left^T + b0
__device__ float d_zbuf[(size_t)BB*TT*ZD];    // sampled z, (b,t,16)
__device__ float d_hdec[(size_t)BB*TT*HH];    // decoder hidden, (b,t,128)
__device__ float d_WTgx[HH*GG];               // Whh_gx transposed (k,j)
__device__ float d_WTgz[HH*GG];
__device__ float d_WTh [HH*GG];
__device__ float d_W0RT[HH*HH];               // right half of W0, transposed (k,j)
__device__ float d_WihTgz[ZD*GG];
__device__ float d_WihTh [ZD*GG];
__device__ float d_bgx[GG];
__device__ float d_bgz[GG];
__device__ float d_bh [GG];

__device__ __forceinline__ float sigf(float x) { return 1.f/(1.f + expf(-x)); }

// ---------------- weight prep: transposes + combined biases ----------------
__global__ void prep_weights(const float* __restrict__ Whh_gx,
                             const float* __restrict__ bih_gx, const float* __restrict__ bhh_gx,
                             const float* __restrict__ Wih_gz, const float* __restrict__ Whh_gz,
                             const float* __restrict__ bih_gz, const float* __restrict__ bhh_gz,
                             const float* __restrict__ W0,
                             const float* __restrict__ Wih_h, const float* __restrict__ Whh_h,
                             const float* __restrict__ bih_h, const float* __restrict__ bhh_h)
{
    int idx = blockIdx.x*blockDim.x + threadIdx.x;
    int stride = gridDim.x*blockDim.x;
    for (int i = idx; i < GG*HH; i += stride) {
        int j = i / HH, k = i % HH;
        d_WTgx[k*GG + j] = Whh_gx[i];
        d_WTgz[k*GG + j] = Whh_gz[i];
        d_WTh [k*GG + j] = Whh_h [i];
    }
    for (int i = idx; i < HH*HH; i += stride) {
        int j = i / HH, k = i % HH;
        d_W0RT[k*HH + j] = W0[j*(2*HH) + HH + k];
    }
    for (int i = idx; i < GG*ZD; i += stride) {
        int j = i / ZD, k = i % ZD;
        d_WihTgz[k*GG + j] = Wih_gz[i];
        d_WihTh [k*GG + j] = Wih_h [i];
    }
    for (int i = idx; i < GG; i += stride) {
        d_bgx[i] = bih_gx[i] + bhh_gx[i];
        d_bgz[i] = bih_gz[i] + bhh_gz[i];
        d_bh [i] = bih_h [i] + bhh_h [i];
    }
}

// ---------------- x transpose: (B,257,T) -> (T,B,257)  [2D transpose of (65792,512)] ----------------
__global__ void __launch_bounds__(256) transpose_x(const float* __restrict__ x)
{
    __shared__ float tile[32][33];
    int r0 = blockIdx.x*32;
    int c0 = blockIdx.y*32;
    int tx = threadIdx.x & 31, ty = threadIdx.x >> 5;  // 32x8
#pragma unroll
    for (int i = 0; i < 32; i += 8)
        tile[ty+i][tx] = x[(size_t)(r0+ty+i)*TT + c0 + tx];
    __syncthreads();
#pragma unroll
    for (int i = 0; i < 32; i += 8)
        d_xT[(size_t)(c0+ty+i)*XROWS + r0 + tx] = tile[tx][ty+i];
}

// ---------------- generic C = A(MxK) * Bw(NxK)^T + bias, fp32 SIMT tiled ----------------
// MODE 0: row-major store C[m*N+n].  MODE 1: y epilogue: exp(), scatter to (B,257,T) with m=(b*512+t).
template<int MODE>
__global__ void __launch_bounds__(256)
gemm_tn(const float* __restrict__ A, int lda,
        const float* __restrict__ Bw, int ldb,
        const float* __restrict__ bias,
        float* __restrict__ C,
        int M, int N, int K)
{
    const int BM = 128, BN = 64, BK = 16;
    __shared__ float As[BK][BM];
    __shared__ float Bs[BK][BN];
    int tid = threadIdx.x;
    int bm = blockIdx.x*BM, bn = blockIdx.y*BN;
    int tm = (tid & 15)*8;
    int tn = (tid >> 4)*4;
    float acc[8][4];
#pragma unroll
    for (int i = 0; i < 8; i++)
#pragma unroll
        for (int j = 0; j < 4; j++) acc[i][j] = 0.f;

    int ar = tid >> 1, ac = (tid & 1)*8;   // A: 128 rows x 16k, 8 scalars/thread
    int br = tid >> 2, bc = (tid & 3)*4;   // B: 64 rows x 16k, 4 scalars/thread

    for (int kk = 0; kk < K; kk += BK) {
#pragma unroll
        for (int i = 0; i < 8; i++) {
            int k = kk + ac + i;
            As[ac+i][ar] = (k < K) ? A[(size_t)(bm+ar)*lda + k] : 0.f;
        }
#pragma unroll
        for (int i = 0; i < 4; i++) {
            int k = kk + bc + i;
            Bs[bc+i][br] = (k < K && (bn+br) < N) ? Bw[(size_t)(bn+br)*ldb + k] : 0.f;
        }
        __syncthreads();
#pragma unroll
        for (int k = 0; k < BK; k++) {
            float a[8], b[4];
#pragma unroll
            for (int i = 0; i < 8; i++) a[i] = As[k][tm+i];
#pragma unroll
            for (int j = 0; j < 4; j++) b[j] = Bs[k][tn+j];
#pragma unroll
            for (int i = 0; i < 8; i++)
#pragma unroll
                for (int j = 0; j < 4; j++)
                    acc[i][j] += a[i]*b[j];
        }
        __syncthreads();
    }

#pragma unroll
    for (int j = 0; j < 4; j++) {
        int n = bn + tn + j;
        if (n >= N) continue;
        float bi = bias[n];
#pragma unroll
        for (int i = 0; i < 8; i++) {
            int m = bm + tm + i;
            float v = acc[i][j] + bi;
            if (MODE == 0) {
                C[(size_t)m*N + n] = v;
            } else {
                int b = m >> 9;        // m = b*512 + t
                int t = m & 511;
                C[(size_t)b*XD*TT + (size_t)n*TT + t] = expf(v);
            }
        }
    }
}

// ---------------- phase B: backward LSTM over x-gates -> gx ----------------
__global__ void __launch_bounds__(256) lstm_gx_kernel()
{
    __shared__ float h_s[RB][HH];
    __shared__ float g_s[RB][GG];
    int tid = threadIdx.x;
    int b0 = blockIdx.x*RB;
    for (int i = tid; i < RB*HH; i += 256) h_s[i/HH][i%HH] = 0.f;
    float c0 = 0.f, c1 = 0.f;
    __syncthreads();

    for (int t = TT-1; t >= 0; --t) {
        const float* prow = d_gates + ((size_t)t*BB + b0)*GG;
        float acc0[RB], acc1[RB];
#pragma unroll
        for (int r = 0; r < RB; r++) { acc0[r] = prow[r*GG + tid]; acc1[r] = prow[r*GG + tid + 256]; }
#pragma unroll 8
        for (int k = 0; k < HH; k++) {
            float w0 = d_WTgx[k*GG + tid];
            float w1 = d_WTgx[k*GG + tid + 256];
#pragma unroll
            for (int r = 0; r < RB; r++) {
                float h = h_s[r][k];
                acc0[r] += w0*h;
                acc1[r] += w1*h;
            }
        }
#pragma unroll
        for (int r = 0; r < RB; r++) { g_s[r][tid] = acc0[r]; g_s[r][tid+256] = acc1[r]; }
        __syncthreads();
        {   // unit tid
            int r = tid >> 7, hi = tid & 127;
            float i_ = sigf(g_s[r][hi]);
            float f_ = sigf(g_s[r][HH + hi]);
            float gg = tanhf(g_s[r][2*HH + hi]);
            float o_ = sigf(g_s[r][3*HH + hi]);
            c0 = f_*c0 + i_*gg;
            float h = o_*tanhf(c0);
            h_s[r][hi] = h;
            d_gx[((size_t)t*BB + b0 + r)*HH + hi] = h;
        }
        {   // unit tid+256
            int u = tid + 256;
            int r = u >> 7, hi = u & 127;
            float i_ = sigf(g_s[r][hi]);
            float f_ = sigf(g_s[r][HH + hi]);
            float gg = tanhf(g_s[r][2*HH + hi]);
            float o_ = sigf(g_s[r][3*HH + hi]);
            c1 = f_*c1 + i_*gg;
            float h = o_*tanhf(c1);
            h_s[r][hi] = h;
            d_gx[((size_t)t*BB + b0 + r)*HH + hi] = h;
        }
        __syncthreads();
    }
}

// ---------------- phase C: inference loop (MLP, heads, reparam, g_z LSTM cell) ----------------
__global__ void __launch_bounds__(256) inference_kernel(
    const float* __restrict__ eps,
    const float* __restrict__ Wm, const float* __restrict__ bm,
    const float* __restrict__ Wv, const float* __restrict__ bv,
    float* __restrict__ out_mean, float* __restrict__ out_logvar, float* __restrict__ out_z)
{
    __shared__ float h_s[RB][HH];     // g_z
    __shared__ float hm_s[RB][HH];    // mlp hidden
    __shared__ float mv_s[RB][2][ZD];
    __shared__ float z_s[RB][ZD];
    __shared__ float g_s[RB][GG];
    int tid = threadIdx.x;
    int b0 = blockIdx.x*RB;
    for (int i = tid; i < RB*HH; i += 256) h_s[i/HH][i%HH] = 0.f;
    float c0 = 0.f, c1 = 0.f;
    __syncthreads();

    for (int t = 0; t < TT; ++t) {
        // 1: h = tanh(u0 + g_z @ W0R^T)  (uses OLD g_z, as in reference)
        {
            int j0 = tid & 127, rh = tid >> 7;
            int r0 = rh*2, r1 = rh*2 + 1;
            float a0 = d_u0[((size_t)t*BB + b0 + r0)*HH + j0];
            float a1 = d_u0[((size_t)t*BB + b0 + r1)*HH + j0];
#pragma unroll 8
            for (int k = 0; k < HH; k++) {
                float w = d_W0RT[k*HH + j0];
                a0 += w*h_s[r0][k];
                a1 += w*h_s[r1][k];
            }
            hm_s[r0][j0] = tanhf(a0);
            hm_s[r1][j0] = tanhf(a1);
        }
        __syncthreads();
        // 2: mean / logvar heads
        if (tid < 128) {
            int r = tid >> 5, head = (tid >> 4) & 1, zi = tid & 15;
            const float* W = head ? Wv : Wm;
            float acc = head ? bv[zi] : bm[zi];
#pragma unroll 8
            for (int k = 0; k < HH; k++) acc += W[zi*HH + k]*hm_s[r][k];
            mv_s[r][head][zi] = acc;
        }
        __syncthreads();
        // 3: reparameterize + write outputs
        if (tid < RB*ZD) {
            int r = tid >> 4, zi = tid & 15;
            float mn = mv_s[r][0][zi], lv = mv_s[r][1][zi];
            float e = eps[((size_t)t*BB + b0 + r)*ZD + zi];
            float zv = e*expf(0.5f*lv) + mn;
            z_s[r][zi] = zv;
            int b = b0 + r;
            size_t oidx = (size_t)b*ZD*TT + (size_t)zi*TT + t;
            out_mean[oidx]   = mn;
            out_logvar[oidx] = lv;
            out_z[oidx]      = zv;
            d_zbuf[((size_t)b*TT + t)*ZD + zi] = zv;
        }
        __syncthreads();
        // 4: g_z LSTM-cell gates (input z_t, hidden OLD g_z)
        {
            float acc0[RB], acc1[RB];
#pragma unroll
            for (int r = 0; r < RB; r++) { acc0[r] = d_bgz[tid]; acc1[r] = d_bgz[tid+256]; }
#pragma unroll
            for (int k = 0; k < ZD; k++) {
                float w0 = d_WihTgz[k*GG + tid];
                float w1 = d_WihTgz[k*GG + tid + 256];
#pragma unroll
                for (int r = 0; r < RB; r++) { float z = z_s[r][k]; acc0[r] += w0*z; acc1[r] += w1*z; }
            }
#pragma unroll 8
            for (int k = 0; k < HH; k++) {
                float w0 = d_WTgz[k*GG + tid];
                float w1 = d_WTgz[k*GG + tid + 256];
#pragma unroll
                for (int r = 0; r < RB; r++) { float h = h_s[r][k]; acc0[r] += w0*h; acc1[r] += w1*h; }
            }
#pragma unroll
            for (int r = 0; r < RB; r++) { g_s[r][tid] = acc0[r]; g_s[r][tid+256] = acc1[r]; }
        }
        __syncthreads();
        // 5: state update
        {
            int r = tid >> 7, hi = tid & 127;
            float i_ = sigf(g_s[r][hi]);
            float f_ = sigf(g_s[r][HH + hi]);
            float gg = tanhf(g_s[r][2*HH + hi]);
            float o_ = sigf(g_s[r][3*HH + hi]);
            c0 = f_*c0 + i_*gg;
            h_s[r][hi] = o_*tanhf(c0);
        }
        {
            int u = tid + 256;
            int r = u >> 7, hi = u & 127;
            float i_ = sigf(g_s[r][hi]);
            float f_ = sigf(g_s[r][HH + hi]);
            float gg = tanhf(g_s[r][2*HH + hi]);
            float o_ = sigf(g_s[r][3*HH + hi]);
            c1 = f_*c1 + i_*gg;
            h_s[r][hi] = o_*tanhf(c1);
        }
        __syncthreads();
    }
}

// ---------------- phase E: forward decoder LSTM over z -> hdec ----------------
__global__ void __launch_bounds__(256) lstm_dec_kernel()
{
    __shared__ float h_s[RB][HH];
    __shared__ float z_s[RB][ZD];
    __shared__ float g_s[RB][GG];
    int tid = threadIdx.x;
    int b0 = blockIdx.x*RB;
    for (int i = tid; i < RB*HH; i += 256) h_s[i/HH][i%HH] = 0.f;
    float c0 = 0.f, c1 = 0.f;
    __syncthreads();

    for (int t = 0; t < TT; ++t) {
        if (tid < RB*ZD) {
            int r = tid / ZD, zi = tid % ZD;
            z_s[r][zi] = d_zbuf[((size_t)(b0+r)*TT + t)*ZD + zi];
        }
        __syncthreads();
        float acc0[RB], acc1[RB];
#pragma unroll
        for (int r = 0; r < RB; r++) { acc0[r] = d_bh[tid]; acc1[r] = d_bh[tid+256]; }
#pragma unroll
        for (int k = 0; k < ZD; k++) {
            float w0 = d_WihTh[k*GG + tid];
            float w1 = d_WihTh[k*GG + tid + 256];
#pragma unroll
            for (int r = 0; r < RB; r++) { float z = z_s[r][k]; acc0[r] += w0*z; acc1[r] += w1*z; }
        }
#pragma unroll 8
        for (int k = 0; k < HH; k++) {
            float w0 = d_WTh[k*GG + tid];
            float w1 = d_WTh[k*GG + tid + 256];
#pragma unroll
            for (int r = 0; r < RB; r++) { float h = h_s[r][k]; acc0[r] += w0*h; acc1[r] += w1*h; }
        }
#pragma unroll
        for (int r = 0; r < RB; r++) { g_s[r][tid] = acc0[r]; g_s[r][tid+256] = acc1[r]; }
        __syncthreads();
        {
            int r = tid >> 7, hi = tid & 127;
            float i_ = sigf(g_s[r][hi]);
            float f_ = sigf(g_s[r][HH + hi]);
            float gg = tanhf(g_s[r][2*HH + hi]);
            float o_ = sigf(g_s[r][3*HH + hi]);
            c0 = f_*c0 + i_*gg;
            float h = o_*tanhf(c0);
            h_s[r][hi] = h;
            d_hdec[((size_t)(b0+r)*TT + t)*HH + hi] = h;
        }
        {
            int u = tid + 256;
            int r = u >> 7, hi = u & 127;
            float i_ = sigf(g_s[r][hi]);
            float f_ = sigf(g_s[r][HH + hi]);
            float gg = tanhf(g_s[r][2*HH + hi]);
            float o_ = sigf(g_s[r][3*HH + hi]);
            c1 = f_*c1 + i_*gg;
            float h = o_*tanhf(c1);
            h_s[r][hi] = h;
            d_hdec[((size_t)(b0+r)*TT + t)*HH + hi] = h;
        }
        __syncthreads();
    }
}

// ---------------- host launcher ----------------
extern "C" void kernel_launch(void* const* d_in, const int* in_sizes, int n_in,
                              void* d_out, int out_size)
{
    (void)in_sizes; (void)n_in; (void)out_size;
    const float* x      = (const float*)d_in[0];
    const float* eps    = (const float*)d_in[1];
    const float* Wih_gx = (const float*)d_in[2];
    const float* Whh_gx = (const float*)d_in[3];
    const float* bih_gx = (const float*)d_in[4];
    const float* bhh_gx = (const float*)d_in[5];
    const float* Wih_gz = (const float*)d_in[6];
    const float* Whh_gz = (const float*)d_in[7];
    const float* bih_gz = (const float*)d_in[8];
    const float* bhh_gz = (const float*)d_in[9];
    const float* W0     = (const float*)d_in[10];
    const float* b0     = (const float*)d_in[11];
    const float* Wm     = (const float*)d_in[12];
    const float* bm     = (const float*)d_in[13];
    const float* Wv     = (const float*)d_in[14];
    const float* bv     = (const float*)d_in[15];
    const float* Wih_h  = (const float*)d_in[16];
    const float* Whh_h  = (const float*)d_in[17];
    const float* bih_h  = (const float*)d_in[18];
    const float* bhh_h  = (const float*)d_in[19];
    const float* Wy     = (const float*)d_in[20];
    const float* by     = (const float*)d_in[21];

    float *p_xT, *p_gates, *p_gx, *p_u0, *p_hdec, *p_bgx;
    cudaGetSymbolAddress((void**)&p_xT,    d_xT);
    cudaGetSymbolAddress((void**)&p_gates, d_gates);
    cudaGetSymbolAddress((void**)&p_gx,    d_gx);
    cudaGetSymbolAddress((void**)&p_u0,    d_u0);
    cudaGetSymbolAddress((void**)&p_hdec,  d_hdec);
    cudaGetSymbolAddress((void**)&p_bgx,   d_bgx);

    float* out = (float*)d_out;
    const size_t Y_SZ  = (size_t)BB*XD*TT;
    const size_t MV_SZ = (size_t)BB*ZD*TT;

    // 0) weight prep + x transpose
    prep_weights<<<64, 256>>>(Whh_gx, bih_gx, bhh_gx, Wih_gz, Whh_gz, bih_gz, bhh_gz,
                              W0, Wih_h, Whh_h, bih_h, bhh_h);
    transpose_x<<<dim3(XROWS/32, TT/32), 256>>>(x);

    // A) input gates for backward LSTM: (T*B,512) = xT(257) @ Wih_gx^T + (bih+bhh)
    gemm_tn<0><<<dim3(TT*BB/128, GG/64), 256>>>(p_xT, XD, Wih_gx, XD, p_bgx, p_gates,
                                                TT*BB, GG, XD);
    // B) backward LSTM -> gx
    lstm_gx_kernel<<<NBLK, 256>>>();
    // B2) u0 = gx @ W0_left^T + b0   (W0 is (H, 2H) row-major, ldb = 2H selects left half)
    gemm_tn<0><<<dim3(TT*BB/128, HH/64), 256>>>(p_gx, HH, W0, 2*HH, b0, p_u0,
                                                TT*BB, HH, HH);
    // C) inference loop (mean/logvar/z outputs + z_buf)
    inference_kernel<<<NBLK, 256>>>(eps, Wm, bm, Wv, bv,
                                    out + Y_SZ, out + Y_SZ + MV_SZ, out + Y_SZ + 2*MV_SZ);
    // E) decoder LSTM -> hdec (b,t order)
    lstm_dec_kernel<<<NBLK, 256>>>();
    // F) y = exp(hdec @ Wy^T + by), scattered to (B,257,T)
    gemm_tn<1><<<dim3(TT*BB/128, (XD+63)/64), 256>>>(p_hdec, HH, Wy, HH, by, out,
                                                     TT*BB, XD, HH);
}

// round 4
// speedup vs baseline: 2.9184x; 2.9184x over previous
#include <cuda_runtime.h>
#include <math.h>
#include <stdint.h>

#define TT 512
#define BB 256
#define HH 128
#define XD 257
#define ZD 16
#define GG 512         // 4*H
#define RB 4           // batch rows per cluster
#define NCLUST (BB/RB) // 64 clusters -> 128 CTAs
#define XROWS (BB*XD)  // 65792

// ---------------- scratch ----------------
__device__ float d_xT[(size_t)TT*BB*XD];      // (t,b,257)
__device__ float d_gates[(size_t)TT*BB*GG];   // input gates for bwd LSTM
__device__ float d_gx[(size_t)TT*BB*HH];      // (t,b,128)
__device__ float d_u0[(size_t)TT*BB*HH];      // gx @ W0L^T + b0, (t,b,128)
__device__ float d_zbuf[(size_t)BB*TT*ZD];    // (b,t,16)
__device__ float d_hdec[(size_t)BB*TT*HH];    // (b,t,128)
__device__ float d_WTgx[HH*GG];               // [k][512]
__device__ float d_WTgz[HH*GG];
__device__ float d_WTh [HH*GG];
__device__ float d_W0RT[HH*HH];               // [k][j]
__device__ float d_WihTgz[ZD*GG];             // [k][512]
__device__ float d_WihTh [ZD*GG];
__device__ float d_bgx[GG];
__device__ float d_bgz[GG];
__device__ float d_bh [GG];

__device__ __forceinline__ float sigf(float x) { return 1.f/(1.f + expf(-x)); }

// ---- f32x2 + cluster helpers ----
__device__ __forceinline__ unsigned long long pk2(float lo, float hi) {
    unsigned long long r; asm("mov.b64 %0, {%1, %2};" : "=l"(r) : "f"(lo), "f"(hi)); return r;
}
__device__ __forceinline__ void upk2(unsigned long long v, float& lo, float& hi) {
    asm("mov.b64 {%0, %1}, %2;" : "=f"(lo), "=f"(hi) : "l"(v));
}
__device__ __forceinline__ unsigned long long f2fma(unsigned long long a, unsigned long long b, unsigned long long c) {
    unsigned long long d; asm("fma.rn.f32x2 %0, %1, %2, %3;" : "=l"(d) : "l"(a), "l"(b), "l"(c)); return d;
}
__device__ __forceinline__ uint32_t s2u(const void* p) {
    uint32_t a; asm("{ .reg .u64 t; cvta.to.shared.u64 t, %1; cvt.u32.u64 %0, t; }" : "=r"(a) : "l"(p)); return a;
}
__device__ __forceinline__ uint32_t mapa_u32(uint32_t a, uint32_t rk) {
    uint32_t o; asm("mapa.shared::cluster.u32 %0, %1, %2;" : "=r"(o) : "r"(a), "r"(rk)); return o;
}
__device__ __forceinline__ void stpeer(uint32_t a, float v) {
    asm volatile("st.shared::cluster.f32 [%0], %1;" :: "r"(a), "f"(v) : "memory");
}
#define CLUSTER_SYNC() do { \
    asm volatile("barrier.cluster.arrive.aligned;" ::: "memory"); \
    asm volatile("barrier.cluster.wait.aligned;"   ::: "memory"); } while (0)

// ---------------- weight prep ----------------
__global__ void prep_weights(const float* __restrict__ Whh_gx,
                             const float* __restrict__ bih_gx, const float* __restrict__ bhh_gx,
                             const float* __restrict__ Wih_gz, const float* __restrict__ Whh_gz,
                             const float* __restrict__ bih_gz, const float* __restrict__ bhh_gz,
                             const float* __restrict__ W0,
                             const float* __restrict__ Wih_h, const float* __restrict__ Whh_h,
                             const float* __restrict__ bih_h, const float* __restrict__ bhh_h)
{
    int idx = blockIdx.x*blockDim.x + threadIdx.x;
    int stride = gridDim.x*blockDim.x;
    for (int i = idx; i < GG*HH; i += stride) {
        int j = i / HH, k = i % HH;
        d_WTgx[k*GG + j] = Whh_gx[i];
        d_WTgz[k*GG + j] = Whh_gz[i];
        d_WTh [k*GG + j] = Whh_h [i];
    }
    for (int i = idx; i < HH*HH; i += stride) {
        int j = i / HH, k = i % HH;
        d_W0RT[k*HH + j] = W0[j*(2*HH) + HH + k];
    }
    for (int i = idx; i < GG*ZD; i += stride) {
        int j = i / ZD, k = i % ZD;
        d_WihTgz[k*GG + j] = Wih_gz[i];
        d_WihTh [k*GG + j] = Wih_h [i];
    }
    for (int i = idx; i < GG; i += stride) {
        d_bgx[i] = bih_gx[i] + bhh_gx[i];
        d_bgz[i] = bih_gz[i] + bhh_gz[i];
        d_bh [i] = bih_h [i] + bhh_h [i];
    }
}

// ---------------- x transpose ----------------
__global__ void __launch_bounds__(256) transpose_x(const float* __restrict__ x)
{
    __shared__ float tile[32][33];
    int r0 = blockIdx.x*32;
    int c0 = blockIdx.y*32;
    int tx = threadIdx.x & 31, ty = threadIdx.x >> 5;
#pragma unroll
    for (int i = 0; i < 32; i += 8)
        tile[ty+i][tx] = x[(size_t)(r0+ty+i)*TT + c0 + tx];
    __syncthreads();
#pragma unroll
    for (int i = 0; i < 32; i += 8)
        d_xT[(size_t)(c0+ty+i)*XROWS + r0 + tx] = tile[tx][ty+i];
}

// ---------------- GEMM C = A(MxK) * Bw(NxK)^T + bias, f32x2 packed ----------------
template<int MODE>
__global__ void __launch_bounds__(256)
gemm_tn(const float* __restrict__ A, int lda,
        const float* __restrict__ Bw, int ldb,
        const float* __restrict__ bias,
        float* __restrict__ C,
        int M, int N, int K)
{
    const int BM = 128, BN = 64, BK = 16;
    __shared__ float As[BK][BM];
    __shared__ unsigned long long Bs2[BK][BN];   // duplicated pairs (b,b)
    int tid = threadIdx.x;
    int bm = blockIdx.x*BM, bn = blockIdx.y*BN;
    int tm = (tid & 15)*8;
    int tn = (tid >> 4)*4;
    unsigned long long acc[4][4];
#pragma unroll
    for (int p = 0; p < 4; p++)
#pragma unroll
        for (int j = 0; j < 4; j++) acc[p][j] = 0ull;

    int ar = tid >> 1, ac = (tid & 1)*8;
    int br = tid >> 2, bc = (tid & 3)*4;

    for (int kk = 0; kk < K; kk += BK) {
#pragma unroll
        for (int i = 0; i < 8; i++) {
            int k = kk + ac + i;
            As[ac+i][ar] = (k < K) ? A[(size_t)(bm+ar)*lda + k] : 0.f;
        }
#pragma unroll
        for (int i = 0; i < 4; i++) {
            int k = kk + bc + i;
            float bv = (k < K && (bn+br) < N) ? Bw[(size_t)(bn+br)*ldb + k] : 0.f;
            Bs2[bc+i][br] = pk2(bv, bv);
        }
        __syncthreads();
#pragma unroll
        for (int k = 0; k < BK; k++) {
            ulonglong2 aA = *(const ulonglong2*)(&As[k][tm]);
            ulonglong2 aB = *(const ulonglong2*)(&As[k][tm+4]);
            ulonglong2 b01 = *(const ulonglong2*)(&Bs2[k][tn]);
            ulonglong2 b23 = *(const ulonglong2*)(&Bs2[k][tn+2]);
            acc[0][0] = f2fma(aA.x, b01.x, acc[0][0]);
            acc[1][0] = f2fma(aA.y, b01.x, acc[1][0]);
            acc[2][0] = f2fma(aB.x, b01.x, acc[2][0]);
            acc[3][0] = f2fma(aB.y, b01.x, acc[3][0]);
            acc[0][1] = f2fma(aA.x, b01.y, acc[0][1]);
            acc[1][1] = f2fma(aA.y, b01.y, acc[1][1]);
            acc[2][1] = f2fma(aB.x, b01.y, acc[2][1]);
            acc[3][1] = f2fma(aB.y, b01.y, acc[3][1]);
            acc[0][2] = f2fma(aA.x, b23.x, acc[0][2]);
            acc[1][2] = f2fma(aA.y, b23.x, acc[1][2]);
            acc[2][2] = f2fma(aB.x, b23.x, acc[2][2]);
            acc[3][2] = f2fma(aB.y, b23.x, acc[3][2]);
            acc[0][3] = f2fma(aA.x, b23.y, acc[0][3]);
            acc[1][3] = f2fma(aA.y, b23.y, acc[1][3]);
            acc[2][3] = f2fma(aB.x, b23.y, acc[2][3]);
            acc[3][3] = f2fma(aB.y, b23.y, acc[3][3]);
        }
        __syncthreads();
    }

#pragma unroll
    for (int j = 0; j < 4; j++) {
        int n = bn + tn + j;
        if (n >= N) continue;
        float bi = bias[n];
#pragma unroll
        for (int p = 0; p < 4; p++) {
            float v0, v1; upk2(acc[p][j], v0, v1);
            int m0 = bm + tm + 2*p;
            if (MODE == 0) {
                C[(size_t)m0*N + n]     = v0 + bi;
                C[(size_t)(m0+1)*N + n] = v1 + bi;
            } else {
                int b = m0 >> 9, t = m0 & 511;
                C[(size_t)b*XD*TT + (size_t)n*TT + t] = expf(v0 + bi);
                int m1 = m0 + 1;
                b = m1 >> 9; t = m1 & 511;
                C[(size_t)b*XD*TT + (size_t)n*TT + t] = expf(v1 + bi);
            }
        }
    }
}

// ======== shared-memory layouts for cluster LSTM kernels (float offsets) ========
#define SM_WH    0          // [128][256]  this rank's Whh^T half
#define SM_H4    32768      // [128][4]    h pairs (r0,r1,r2,r3)
#define SM_GLOC  33280      // [256][5]    own gate half
#define SM_GEX   34560      // [2][256][5] peer-written gate half (parity dbl-buf)
#define SM_Z4    37120      // [16][4]
#define SMB_LSTM ((37184)*4)

#define SMI_W0R  32768      // [128][128]
#define SMI_H4   49152
#define SMI_GLOC 49664
#define SMI_GEX  50944
#define SMI_HM   53504      // [2][128]
#define SMI_MV   53760      // [64]
#define SMI_Z4   53824      // [16][4]
#define SMB_INF  ((53888)*4)

// ---------------- backward LSTM over precomputed gates -> gx ----------------
__global__ void __launch_bounds__(256,1) __cluster_dims__(2,1,1)
lstm_gx_kernel()
{
    extern __shared__ float sm[];
    float* WH = sm + SM_WH;
    float* h4 = sm + SM_H4;
    float* gl = sm + SM_GLOC;
    float* ge = sm + SM_GEX;
    int tid = threadIdx.x;
    uint32_t rank = blockIdx.x & 1u;
    int b0 = (blockIdx.x >> 1) * RB;

    for (int k = 0; k < HH; k++)
        WH[k*256 + tid] = d_WTgx[k*GG + rank*256 + tid];
    for (int i = tid; i < 512; i += 256) h4[i] = 0.f;
    float c0 = 0.f, c1 = 0.f;
    uint32_t ge_peer = mapa_u32(s2u(ge), rank ^ 1u);
    CLUSTER_SYNC();

    for (int t = TT-1; t >= 0; --t) {
        const float* prow = d_gates + ((size_t)t*BB + b0)*GG + rank*256 + tid;
        float p0 = prow[0], p1 = prow[GG], p2 = prow[2*GG], p3 = prow[3*GG];
        unsigned long long a01 = pk2(p0, p1), a23 = pk2(p2, p3);
#pragma unroll 16
        for (int k = 0; k < HH; k++) {
            float w = WH[k*256 + tid];
            unsigned long long wp = pk2(w, w);
            ulonglong2 hp = *(const ulonglong2*)(h4 + k*4);
            a01 = f2fma(wp, hp.x, a01);
            a23 = f2fma(wp, hp.y, a23);
        }
        float g0, g1, g2, g3; upk2(a01, g0, g1); upk2(a23, g2, g3);
        int par = t & 1;
        int base = tid*5;
        gl[base+0]=g0; gl[base+1]=g1; gl[base+2]=g2; gl[base+3]=g3;
        uint32_t pa = ge_peer + (uint32_t)(par*1280 + base)*4u;
        stpeer(pa, g0); stpeer(pa+4u, g1); stpeer(pa+8u, g2); stpeer(pa+12u, g3);
        CLUSTER_SYNC();
        const float* gif = rank ? (ge + par*1280) : gl;
        const float* ggo = rank ? gl : (ge + par*1280);
        {
            int u = tid, r = u >> 7, hi = u & 127;
            float i_ = sigf(gif[hi*5+r]);
            float f_ = sigf(gif[(128+hi)*5+r]);
            float g_ = tanhf(ggo[hi*5+r]);
            float o_ = sigf(ggo[(128+hi)*5+r]);
            c0 = f_*c0 + i_*g_;
            float h = o_*tanhf(c0);
            h4[hi*4+r] = h;
            if (!rank) d_gx[((size_t)t*BB + b0 + r)*HH + hi] = h;
        }
        {
            int u = tid + 256, r = u >> 7, hi = u & 127;
            float i_ = sigf(gif[hi*5+r]);
            float f_ = sigf(gif[(128+hi)*5+r]);
            float g_ = tanhf(ggo[hi*5+r]);
            float o_ = sigf(ggo[(128+hi)*5+r]);
            c1 = f_*c1 + i_*g_;
            float h = o_*tanhf(c1);
            h4[hi*4+r] = h;
            if (!rank) d_gx[((size_t)t*BB + b0 + r)*HH + hi] = h;
        }
        __syncthreads();
    }
}

// ---------------- decoder LSTM over z -> hdec ----------------
__global__ void __launch_bounds__(256,1) __cluster_dims__(2,1,1)
lstm_dec_kernel()
{
    extern __shared__ float sm[];
    float* WH = sm + SM_WH;
    float* h4 = sm + SM_H4;
    float* gl = sm + SM_GLOC;
    float* ge = sm + SM_GEX;
    float* z4 = sm + SM_Z4;
    int tid = threadIdx.x;
    uint32_t rank = blockIdx.x & 1u;
    int b0 = (blockIdx.x >> 1) * RB;

    for (int k = 0; k < HH; k++)
        WH[k*256 + tid] = d_WTh[k*GG + rank*256 + tid];
    float wz[ZD];
#pragma unroll
    for (int k = 0; k < ZD; k++) wz[k] = d_WihTh[k*GG + rank*256 + tid];
    float bg = d_bh[rank*256 + tid];
    for (int i = tid; i < 512; i += 256) h4[i] = 0.f;
    if (tid < RB*ZD) {   // z for t=0
        int r = tid >> 4, zi = tid & 15;
        z4[zi*4 + r] = d_zbuf[((size_t)(b0+r)*TT + 0)*ZD + zi];
    }
    float c0 = 0.f, c1 = 0.f;
    uint32_t ge_peer = mapa_u32(s2u(ge), rank ^ 1u);
    CLUSTER_SYNC();

    for (int t = 0; t < TT; ++t) {
        unsigned long long a01 = pk2(bg, bg), a23 = a01;
#pragma unroll
        for (int k = 0; k < ZD; k++) {
            unsigned long long wp = pk2(wz[k], wz[k]);
            ulonglong2 zp = *(const ulonglong2*)(z4 + k*4);
            a01 = f2fma(wp, zp.x, a01);
            a23 = f2fma(wp, zp.y, a23);
        }
#pragma unroll 16
        for (int k = 0; k < HH; k++) {
            float w = WH[k*256 + tid];
            unsigned long long wp = pk2(w, w);
            ulonglong2 hp = *(const ulonglong2*)(h4 + k*4);
            a01 = f2fma(wp, hp.x, a01);
            a23 = f2fma(wp, hp.y, a23);
        }
        float g0, g1, g2, g3; upk2(a01, g0, g1); upk2(a23, g2, g3);
        int par = t & 1;
        int base = tid*5;
        gl[base+0]=g0; gl[base+1]=g1; gl[base+2]=g2; gl[base+3]=g3;
        uint32_t pa = ge_peer + (uint32_t)(par*1280 + base)*4u;
        stpeer(pa, g0); stpeer(pa+4u, g1); stpeer(pa+8u, g2); stpeer(pa+12u, g3);
        CLUSTER_SYNC();
        const float* gif = rank ? (ge + par*1280) : gl;
        const float* ggo = rank ? gl : (ge + par*1280);
        {
            int u = tid, r = u >> 7, hi = u & 127;
            float i_ = sigf(gif[hi*5+r]);
            float f_ = sigf(gif[(128+hi)*5+r]);
            float g_ = tanhf(ggo[hi*5+r]);
            float o_ = sigf(ggo[(128+hi)*5+r]);
            c0 = f_*c0 + i_*g_;
            float h = o_*tanhf(c0);
            h4[hi*4+r] = h;
            if (!rank) d_hdec[((size_t)(b0+r)*TT + t)*HH + hi] = h;
        }
        {
            int u = tid + 256, r = u >> 7, hi = u & 127;
            float i_ = sigf(gif[hi*5+r]);
            float f_ = sigf(gif[(128+hi)*5+r]);
            float g_ = tanhf(ggo[hi*5+r]);
            float o_ = sigf(ggo[(128+hi)*5+r]);
            c1 = f_*c1 + i_*g_;
            float h = o_*tanhf(c1);
            h4[hi*4+r] = h;
            if (!rank) d_hdec[((size_t)(b0+r)*TT + t)*HH + hi] = h;
        }
        if (t+1 < TT && tid < RB*ZD) {
            int r = tid >> 4, zi = tid & 15;
            z4[zi*4 + r] = d_zbuf[((size_t)(b0+r)*TT + (t+1))*ZD + zi];
        }
        __syncthreads();
    }
}

// ---------------- inference loop ----------------
__global__ void __launch_bounds__(256,1) __cluster_dims__(2,1,1)
inference_kernel(const float* __restrict__ eps,
                 const float* __restrict__ Wm, const float* __restrict__ bm,
                 const float* __restrict__ Wv, const float* __restrict__ bv,
                 float* __restrict__ out_mean, float* __restrict__ out_logvar,
                 float* __restrict__ out_z)
{
    extern __shared__ float sm[];
    float* WH  = sm + SM_WH;     // Whh_gz^T half
    float* W0R = sm + SMI_W0R;
    float* h4  = sm + SMI_H4;
    float* gl  = sm + SMI_GLOC;
    float* ge  = sm + SMI_GEX;
    float* hm  = sm + SMI_HM;
    float* mv  = sm + SMI_MV;
    float* z4  = sm + SMI_Z4;
    int tid = threadIdx.x;
    uint32_t rank = blockIdx.x & 1u;
    int b0 = (blockIdx.x >> 1) * RB;

    for (int k = 0; k < HH; k++)
        WH[k*256 + tid] = d_WTgz[k*GG + rank*256 + tid];
    for (int i = tid; i < HH*HH; i += 256) W0R[i] = d_W0RT[i];
    float wz[ZD];
#pragma unroll
    for (int k = 0; k < ZD; k++) wz[k] = d_WihTgz[k*GG + rank*256 + tid];
    float bg = d_bgz[rank*256 + tid];
    // head constants: out = tid>>2 in {rr(1),head(1),zi(4)} bits, kq = tid&3
    int outv = tid >> 2, kq = tid & 3;
    int rr_h = outv >> 5, head = (outv >> 4) & 1, zi_h = outv & 15;
    const float* Whd = head ? Wv : Wm;
    float wmv[32];
#pragma unroll
    for (int kk = 0; kk < 32; kk++) wmv[kk] = Whd[zi_h*HH + kq*32 + kk];
    float hbias = head ? bv[zi_h] : bm[zi_h];

    for (int i = tid; i < 512; i += 256) h4[i] = 0.f;
    float c0 = 0.f, c1 = 0.f;
    uint32_t ge_peer = mapa_u32(s2u(ge), rank ^ 1u);
    uint32_t z4_peer = mapa_u32(s2u(z4), rank ^ 1u);
    CLUSTER_SYNC();

    for (int t = 0; t < TT; ++t) {
        // 1) MLP: rows (rank*2, rank*2+1), 128 output cols
        if (tid < HH) {
            int j = tid;
            size_t ub = ((size_t)t*BB + b0 + rank*2)*HH + j;
            unsigned long long acc = pk2(d_u0[ub], d_u0[ub + HH]);
#pragma unroll 16
            for (int k = 0; k < HH; k++) {
                float w = W0R[k*HH + j];
                unsigned long long wp = pk2(w, w);
                unsigned long long hz = *(const unsigned long long*)(h4 + k*4 + rank*2);
                acc = f2fma(wp, hz, acc);
            }
            float v0, v1; upk2(acc, v0, v1);
            hm[j]      = tanhf(v0);
            hm[HH + j] = tanhf(v1);
        }
        __syncthreads();
        // 2) heads: 64 outputs x 4-way k-split, shfl reduce
        {
            const float* hr = hm + rr_h*HH + kq*32;
            float s0=0.f, s1=0.f, s2=0.f, s3=0.f;
#pragma unroll
            for (int kk = 0; kk < 32; kk += 4) {
                s0 += wmv[kk]  *hr[kk];
                s1 += wmv[kk+1]*hr[kk+1];
                s2 += wmv[kk+2]*hr[kk+2];
                s3 += wmv[kk+3]*hr[kk+3];
            }
            float acc = (s0+s1) + (s2+s3);
            acc += __shfl_xor_sync(0xffffffffu, acc, 1);
            acc += __shfl_xor_sync(0xffffffffu, acc, 2);
            if (kq == 0) mv[outv] = acc + hbias;
        }
        __syncthreads();
        // 3) reparameterize (own 2 rows), exchange z
        if (tid < 2*ZD) {
            int rr = tid >> 4, zi = tid & 15;
            int brow = b0 + rank*2 + rr;
            float mn = mv[rr*32 + zi];
            float lv = mv[rr*32 + 16 + zi];
            float e = eps[((size_t)t*BB + brow)*ZD + zi];
            float zv = e*expf(0.5f*lv) + mn;
            z4[zi*4 + rank*2 + rr] = zv;
            stpeer(z4_peer + (uint32_t)(zi*4 + rank*2 + rr)*4u, zv);
            size_t oidx = (size_t)brow*ZD*TT + (size_t)zi*TT + t;
            out_mean[oidx]   = mn;
            out_logvar[oidx] = lv;
            out_z[oidx]      = zv;
            d_zbuf[((size_t)brow*TT + t)*ZD + zi] = zv;
        }
        CLUSTER_SYNC();
        // 4) g_z LSTM gates (z_t + old g_z)
        unsigned long long a01 = pk2(bg, bg), a23 = a01;
#pragma unroll
        for (int k = 0; k < ZD; k++) {
            unsigned long long wp = pk2(wz[k], wz[k]);
            ulonglong2 zp = *(const ulonglong2*)(z4 + k*4);
            a01 = f2fma(wp, zp.x, a01);
            a23 = f2fma(wp, zp.y, a23);
        }
#pragma unroll 16
        for (int k = 0; k < HH; k++) {
            float w = WH[k*256 + tid];
            unsigned long long wp = pk2(w, w);
            ulonglong2 hp = *(const ulonglong2*)(h4 + k*4);
            a01 = f2fma(wp, hp.x, a01);
            a23 = f2fma(wp, hp.y, a23);
        }
        float g0, g1, g2, g3; upk2(a01, g0, g1); upk2(a23, g2, g3);
        int par = t & 1;
        int base = tid*5;
        gl[base+0]=g0; gl[base+1]=g1; gl[base+2]=g2; gl[base+3]=g3;
        uint32_t pa = ge_peer + (uint32_t)(par*1280 + base)*4u;
        stpeer(pa, g0); stpeer(pa+4u, g1); stpeer(pa+8u, g2); stpeer(pa+12u, g3);
        CLUSTER_SYNC();
        const float* gif = rank ? (ge + par*1280) : gl;
        const float* ggo = rank ? gl : (ge + par*1280);
        {
            int u = tid, r = u >> 7, hi = u & 127;
            float i_ = sigf(gif[hi*5+r]);
            float f_ = sigf(gif[(128+hi)*5+r]);
            float g_ = tanhf(ggo[hi*5+r]);
            float o_ = sigf(ggo[(128+hi)*5+r]);
            c0 = f_*c0 + i_*g_;
            h4[hi*4+r] = o_*tanhf(c0);
        }
        {
            int u = tid + 256, r = u >> 7, hi = u & 127;
            float i_ = sigf(gif[hi*5+r]);
            float f_ = sigf(gif[(128+hi)*5+r]);
            float g_ = tanhf(ggo[hi*5+r]);
            float o_ = sigf(gif == gl ? ggo[(128+hi)*5+r] : ggo[(128+hi)*5+r]);
            c1 = f_*c1 + i_*g_;
            h4[hi*4+r] = o_*tanhf(c1);
        }
        __syncthreads();
    }
}

// ---------------- host launcher ----------------
extern "C" void kernel_launch(void* const* d_in, const int* in_sizes, int n_in,
                              void* d_out, int out_size)
{
    (void)in_sizes; (void)n_in; (void)out_size;
    const float* x      = (const float*)d_in[0];
    const float* eps    = (const float*)d_in[1];
    const float* Wih_gx = (const float*)d_in[2];
    const float* Whh_gx = (const float*)d_in[3];
    const float* bih_gx = (const float*)d_in[4];
    const float* bhh_gx = (const float*)d_in[5];
    const float* Wih_gz = (const float*)d_in[6];
    const float* Whh_gz = (const float*)d_in[7];
    const float* bih_gz = (const float*)d_in[8];
    const float* bhh_gz = (const float*)d_in[9];
    const float* W0     = (const float*)d_in[10];
    const float* b0     = (const float*)d_in[11];
    const float* Wm     = (const float*)d_in[12];
    const float* bm     = (const float*)d_in[13];
    const float* Wv     = (const float*)d_in[14];
    const float* bv     = (const float*)d_in[15];
    const float* Wih_h  = (const float*)d_in[16];
    const float* Whh_h  = (const float*)d_in[17];
    const float* bih_h  = (const float*)d_in[18];
    const float* bhh_h  = (const float*)d_in[19];
    const float* Wy     = (const float*)d_in[20];
    const float* by     = (const float*)d_in[21];

    float *p_xT, *p_gates, *p_gx, *p_u0, *p_hdec, *p_bgx;
    cudaGetSymbolAddress((void**)&p_xT,    d_xT);
    cudaGetSymbolAddress((void**)&p_gates, d_gates);
    cudaGetSymbolAddress((void**)&p_gx,    d_gx);
    cudaGetSymbolAddress((void**)&p_u0,    d_u0);
    cudaGetSymbolAddress((void**)&p_hdec,  d_hdec);
    cudaGetSymbolAddress((void**)&p_bgx,   d_bgx);

    cudaFuncSetAttribute(lstm_gx_kernel,   cudaFuncAttributeMaxDynamicSharedMemorySize, SMB_LSTM);
    cudaFuncSetAttribute(lstm_dec_kernel,  cudaFuncAttributeMaxDynamicSharedMemorySize, SMB_LSTM);
    cudaFuncSetAttribute(inference_kernel, cudaFuncAttributeMaxDynamicSharedMemorySize, SMB_INF);

    float* out = (float*)d_out;
    const size_t Y_SZ  = (size_t)BB*XD*TT;
    const size_t MV_SZ = (size_t)BB*ZD*TT;

    prep_weights<<<64, 256>>>(Whh_gx, bih_gx, bhh_gx, Wih_gz, Whh_gz, bih_gz, bhh_gz,
                              W0, Wih_h, Whh_h, bih_h, bhh_h);
    transpose_x<<<dim3(XROWS/32, TT/32), 256>>>(x);

    // A) input gates: (T*B,512) = xT @ Wih_gx^T + (bih+bhh)
    gemm_tn<0><<<dim3(TT*BB/128, GG/64), 256>>>(p_xT, XD, Wih_gx, XD, p_bgx, p_gates,
                                                TT*BB, GG, XD);
    // B) backward LSTM -> gx (clustered)
    lstm_gx_kernel<<<2*NCLUST, 256, SMB_LSTM>>>();
    // B2) u0 = gx @ W0_left^T + b0
    gemm_tn<0><<<dim3(TT*BB/128, HH/64), 256>>>(p_gx, HH, W0, 2*HH, b0, p_u0,
                                                TT*BB, HH, HH);
    // C) inference loop (clustered)
    inference_kernel<<<2*NCLUST, 256, SMB_INF>>>(eps, Wm, bm, Wv, bv,
                                                 out + Y_SZ, out + Y_SZ + MV_SZ,
                                                 out + Y_SZ + 2*MV_SZ);
    // E) decoder LSTM -> hdec (clustered)
    lstm_dec_kernel<<<2*NCLUST, 256, SMB_LSTM>>>();
    // F) y = exp(hdec @ Wy^T + by) -> (B,257,T)
    gemm_tn<1><<<dim3(TT*BB/128, (XD+63)/64), 256>>>(p_hdec, HH, Wy, HH, by, out,
                                                     TT*BB, XD, HH);
}

// round 6
// speedup vs baseline: 3.2428x; 1.1112x over previous
#include <cuda_runtime.h>
#include <math.h>
#include <stdint.h>

#define TT 512
#define BB 256
#define HH 128
#define XD 257
#define ZD 16
#define GG 512         // 4*H
#define RB 4           // batch rows per cluster
#define NCLUST (BB/RB) // 64 clusters -> 128 CTAs
#define XROWS (BB*XD)  // 65792

// ---------------- scratch ----------------
__device__ float d_xT[(size_t)TT*BB*XD];      // (t,b,257)
__device__ float d_gates[(size_t)TT*GG*BB];   // [t][512 gatecol][256 b]
__device__ float d_gx[(size_t)TT*BB*HH];      // (t,b,128)
__device__ float d_u0[(size_t)TT*BB*HH];      // (t,b,128)
__device__ float d_zbuf[(size_t)BB*TT*ZD];    // (b,t,16)
__device__ float d_hdec[(size_t)BB*TT*HH];    // (b,t,128)
__device__ float d_WTgx[HH*GG];               // [k][512]
__device__ float d_WTgz[HH*GG];
__device__ float d_WTh [HH*GG];
__device__ float d_W0RT[HH*HH];               // [k][j]
__device__ float d_WihTgz[ZD*GG];             // [k][512]
__device__ float d_WihTh [ZD*GG];
__device__ float d_bgx[GG];
__device__ float d_bgz[GG];
__device__ float d_bh [GG];

__device__ __forceinline__ float sigf(float x) { return 1.f/(1.f + expf(-x)); }

// ---- f32x2 + cluster helpers ----
__device__ __forceinline__ unsigned long long pk2(float lo, float hi) {
    unsigned long long r; asm("mov.b64 %0, {%1, %2};" : "=l"(r) : "f"(lo), "f"(hi)); return r;
}
__device__ __forceinline__ void upk2(unsigned long long v, float& lo, float& hi) {
    asm("mov.b64 {%0, %1}, %2;" : "=f"(lo), "=f"(hi) : "l"(v));
}
__device__ __forceinline__ unsigned long long f2fma(unsigned long long a, unsigned long long b, unsigned long long c) {
    unsigned long long d; asm("fma.rn.f32x2 %0, %1, %2, %3;" : "=l"(d) : "l"(a), "l"(b), "l"(c)); return d;
}
__device__ __forceinline__ unsigned long long add2(unsigned long long a, unsigned long long b) {
    unsigned long long d; asm("add.rn.f32x2 %0, %1, %2;" : "=l"(d) : "l"(a), "l"(b)); return d;
}
__device__ __forceinline__ uint32_t s2u(const void* p) {
    uint32_t a; asm("{ .reg .u64 t; cvta.to.shared.u64 t, %1; cvt.u32.u64 %0, t; }" : "=r"(a) : "l"(p)); return a;
}
__device__ __forceinline__ uint32_t mapa_u32(uint32_t a, uint32_t rk) {
    uint32_t o; asm("mapa.shared::cluster.u32 %0, %1, %2;" : "=r"(o) : "r"(a), "r"(rk)); return o;
}
__device__ __forceinline__ void stpeer(uint32_t a, float v) {
    asm volatile("st.shared::cluster.f32 [%0], %1;" :: "r"(a), "f"(v) : "memory");
}
#define CLUSTER_SYNC() do { \
    asm volatile("barrier.cluster.arrive.aligned;" ::: "memory"); \
    asm volatile("barrier.cluster.wait.aligned;"   ::: "memory"); } while (0)

// ---------------- weight prep ----------------
__global__ void prep_weights(const float* __restrict__ Whh_gx,
                             const float* __restrict__ bih_gx, const float* __restrict__ bhh_gx,
                             const float* __restrict__ Wih_gz, const float* __restrict__ Whh_gz,
                             const float* __restrict__ bih_gz, const float* __restrict__ bhh_gz,
                             const float* __restrict__ W0,
                             const float* __restrict__ Wih_h, const float* __restrict__ Whh_h,
                             const float* __restrict__ bih_h, const float* __restrict__ bhh_h)
{
    int idx = blockIdx.x*blockDim.x + threadIdx.x;
    int stride = gridDim.x*blockDim.x;
    for (int i = idx; i < GG*HH; i += stride) {
        int j = i / HH, k = i % HH;
        d_WTgx[k*GG + j] = Whh_gx[i];
        d_WTgz[k*GG + j] = Whh_gz[i];
        d_WTh [k*GG + j] = Whh_h [i];
    }
    for (int i = idx; i < HH*HH; i += stride) {
        int j = i / HH, k = i % HH;
        d_W0RT[k*HH + j] = W0[j*(2*HH) + HH + k];
    }
    for (int i = idx; i < GG*ZD; i += stride) {
        int j = i / ZD, k = i % ZD;
        d_WihTgz[k*GG + j] = Wih_gz[i];
        d_WihTh [k*GG + j] = Wih_h [i];
    }
    for (int i = idx; i < GG; i += stride) {
        d_bgx[i] = bih_gx[i] + bhh_gx[i];
        d_bgz[i] = bih_gz[i] + bhh_gz[i];
        d_bh [i] = bih_h [i] + bhh_h [i];
    }
}

// ---------------- x transpose ----------------
__global__ void __launch_bounds__(256) transpose_x(const float* __restrict__ x)
{
    __shared__ float tile[32][33];
    int r0 = blockIdx.x*32;
    int c0 = blockIdx.y*32;
    int tx = threadIdx.x & 31, ty = threadIdx.x >> 5;
#pragma unroll
    for (int i = 0; i < 32; i += 8)
        tile[ty+i][tx] = x[(size_t)(r0+ty+i)*TT + c0 + tx];
    __syncthreads();
#pragma unroll
    for (int i = 0; i < 32; i += 8)
        d_xT[(size_t)(c0+ty+i)*XROWS + r0 + tx] = tile[tx][ty+i];
}

// ---------------- GEMM C = A(MxK) * Bw(NxK)^T + bias, f32x2 packed ----------------
// MODE 0: C[m*N+n]. MODE 1: exp + scatter to (B,257,T). MODE 2: gates layout [t][n][256b].
template<int MODE>
__global__ void __launch_bounds__(256)
gemm_tn(const float* __restrict__ A, int lda,
        const float* __restrict__ Bw, int ldb,
        const float* __restrict__ bias,
        float* __restrict__ C,
        int M, int N, int K)
{
    const int BM = 128, BN = 64, BK = 16;
    __shared__ float As[BK][BM];
    __shared__ unsigned long long Bs2[BK][BN];
    int tid = threadIdx.x;
    int bm = blockIdx.x*BM, bn = blockIdx.y*BN;
    int tm = (tid & 15)*8;
    int tn = (tid >> 4)*4;
    unsigned long long acc[4][4];
#pragma unroll
    for (int p = 0; p < 4; p++)
#pragma unroll
        for (int j = 0; j < 4; j++) acc[p][j] = 0ull;

    int ar = tid >> 1, ac = (tid & 1)*8;
    int br = tid >> 2, bc = (tid & 3)*4;

    for (int kk = 0; kk < K; kk += BK) {
#pragma unroll
        for (int i = 0; i < 8; i++) {
            int k = kk + ac + i;
            As[ac+i][ar] = (k < K) ? A[(size_t)(bm+ar)*lda + k] : 0.f;
        }
#pragma unroll
        for (int i = 0; i < 4; i++) {
            int k = kk + bc + i;
            float bv = (k < K && (bn+br) < N) ? Bw[(size_t)(bn+br)*ldb + k] : 0.f;
            Bs2[bc+i][br] = pk2(bv, bv);
        }
        __syncthreads();
#pragma unroll
        for (int k = 0; k < BK; k++) {
            ulonglong2 aA = *(const ulonglong2*)(&As[k][tm]);
            ulonglong2 aB = *(const ulonglong2*)(&As[k][tm+4]);
            ulonglong2 b01 = *(const ulonglong2*)(&Bs2[k][tn]);
            ulonglong2 b23 = *(const ulonglong2*)(&Bs2[k][tn+2]);
            acc[0][0] = f2fma(aA.x, b01.x, acc[0][0]);
            acc[1][0] = f2fma(aA.y, b01.x, acc[1][0]);
            acc[2][0] = f2fma(aB.x, b01.x, acc[2][0]);
            acc[3][0] = f2fma(aB.y, b01.x, acc[3][0]);
            acc[0][1] = f2fma(aA.x, b01.y, acc[0][1]);
            acc[1][1] = f2fma(aA.y, b01.y, acc[1][1]);
            acc[2][1] = f2fma(aB.x, b01.y, acc[2][1]);
            acc[3][1] = f2fma(aB.y, b01.y, acc[3][1]);
            acc[0][2] = f2fma(aA.x, b23.x, acc[0][2]);
            acc[1][2] = f2fma(aA.y, b23.x, acc[1][2]);
            acc[2][2] = f2fma(aB.x, b23.x, acc[2][2]);
            acc[3][2] = f2fma(aB.y, b23.x, acc[3][2]);
            acc[0][3] = f2fma(aA.x, b23.y, acc[0][3]);
            acc[1][3] = f2fma(aA.y, b23.y, acc[1][3]);
            acc[2][3] = f2fma(aB.x, b23.y, acc[2][3]);
            acc[3][3] = f2fma(aB.y, b23.y, acc[3][3]);
        }
        __syncthreads();
    }

#pragma unroll
    for (int j = 0; j < 4; j++) {
        int n = bn + tn + j;
        if (n >= N) continue;
        float bi = bias[n];
#pragma unroll
        for (int p = 0; p < 4; p++) {
            float v0, v1; upk2(acc[p][j], v0, v1);
            int m0 = bm + tm + 2*p;
            if (MODE == 0) {
                C[(size_t)m0*N + n]     = v0 + bi;
                C[(size_t)(m0+1)*N + n] = v1 + bi;
            } else if (MODE == 2) {
                int t = m0 >> 8, b = m0 & 255;   // m = t*256 + b; pairs never cross t
                C[((size_t)t*GG + n)*BB + b]     = v0 + bi;
                C[((size_t)t*GG + n)*BB + b + 1] = v1 + bi;
            } else {
                int b = m0 >> 9, t = m0 & 511;
                C[(size_t)b*XD*TT + (size_t)n*TT + t] = expf(v0 + bi);
                int m1 = m0 + 1;
                b = m1 >> 9; t = m1 & 511;
                C[(size_t)b*XD*TT + (size_t)n*TT + t] = expf(v1 + bi);
            }
        }
    }
}

// ======== shared layouts (float indices) ========
#define SL_H4    0      // [128][4]
#define SL_GL    512    // [256*5]
#define SL_GE    1792   // [2][256*5]
#define SL_Z4    4352   // [16][4]
#define SL_TOT   4416
#define SMB_LSTM (SL_TOT*4)

#define SI_H4    0      // [128][4]
#define SI_W0R   512    // [128][128]
#define SI_WHD   16896  // [32][132]
#define SI_HM    21120  // [2][128]
#define SI_GL    21376  // [256*5]
#define SI_GE    22656  // [2][256*5]
#define SI_MV    25216  // [64]
#define SI_Z4    25280  // [16][4]
#define SI_TOT   25344
#define SMB_INF  (SI_TOT*4)

// ---------------- backward LSTM over precomputed gates -> gx ----------------
__global__ void __launch_bounds__(256,1) __cluster_dims__(2,1,1)
lstm_gx_kernel()
{
    extern __shared__ float sm[];
    float* h4 = sm + SL_H4;
    float* gl = sm + SL_GL;
    float* ge = sm + SL_GE;
    int tid = threadIdx.x;
    uint32_t rank = blockIdx.x & 1u;
    int b0 = (blockIdx.x >> 1) * RB;
    int col = rank*256 + tid;

    // recurrent weights in registers
    float w[HH];
#pragma unroll
    for (int k = 0; k < HH; k++) w[k] = d_WTgx[k*GG + col];

    for (int i = tid; i < 512; i += 256) h4[i] = 0.f;
    float c0 = 0.f, c1 = 0.f;
    __syncthreads();
    CLUSTER_SYNC();
    uint32_t ge_peer = mapa_u32(s2u(ge), rank ^ 1u);

    float4 pg = *(const float4*)(d_gates + ((size_t)(TT-1)*GG + col)*BB + b0);
    uint32_t s = 0;
    for (int t = TT-1; t >= 0; --t, ++s) {
        float4 cur = pg;
        if (t > 0)
            pg = *(const float4*)(d_gates + ((size_t)(t-1)*GG + col)*BB + b0);
        unsigned long long a01a = pk2(cur.x, cur.y), a23a = pk2(cur.z, cur.w);
        unsigned long long a01b = 0ull, a23b = 0ull;
#pragma unroll
        for (int k = 0; k < HH; k += 2) {
            ulonglong2 hp0 = *(const ulonglong2*)(h4 + k*4);
            ulonglong2 hp1 = *(const ulonglong2*)(h4 + (k+1)*4);
            unsigned long long wp0 = pk2(w[k],   w[k]);
            unsigned long long wp1 = pk2(w[k+1], w[k+1]);
            a01a = f2fma(wp0, hp0.x, a01a);
            a23a = f2fma(wp0, hp0.y, a23a);
            a01b = f2fma(wp1, hp1.x, a01b);
            a23b = f2fma(wp1, hp1.y, a23b);
        }
        float g0, g1, g2, g3;
        upk2(add2(a01a, a01b), g0, g1);
        upk2(add2(a23a, a23b), g2, g3);
        int par = s & 1;
        int base = tid*5;
        gl[base+0]=g0; gl[base+1]=g1; gl[base+2]=g2; gl[base+3]=g3;
        uint32_t pa = ge_peer + (uint32_t)(par*1280 + base)*4u;
        stpeer(pa, g0); stpeer(pa+4u, g1); stpeer(pa+8u, g2); stpeer(pa+12u, g3);
        CLUSTER_SYNC();
        const float* gif = rank ? (ge + par*1280) : gl;
        const float* ggo = rank ? gl : (ge + par*1280);
        {
            int r = tid >> 7, hi = tid & 127;
            float i_ = sigf(gif[hi*5+r]);
            float f_ = sigf(gif[(128+hi)*5+r]);
            float g_ = tanhf(ggo[hi*5+r]);
            float o_ = sigf(ggo[(128+hi)*5+r]);
            c0 = f_*c0 + i_*g_;
            float h = o_*tanhf(c0);
            h4[hi*4+r] = h;
            if (!rank) d_gx[((size_t)t*BB + b0 + r)*HH + hi] = h;
        }
        {
            int u = tid + 256, r = u >> 7, hi = u & 127;
            float i_ = sigf(gif[hi*5+r]);
            float f_ = sigf(gif[(128+hi)*5+r]);
            float g_ = tanhf(ggo[hi*5+r]);
            float o_ = sigf(ggo[(128+hi)*5+r]);
            c1 = f_*c1 + i_*g_;
            float h = o_*tanhf(c1);
            h4[hi*4+r] = h;
            if (!rank) d_gx[((size_t)t*BB + b0 + r)*HH + hi] = h;
        }
        __syncthreads();
    }
}

// ---------------- decoder LSTM over z -> hdec ----------------
__global__ void __launch_bounds__(256,1) __cluster_dims__(2,1,1)
lstm_dec_kernel()
{
    extern __shared__ float sm[];
    float* h4 = sm + SL_H4;
    float* gl = sm + SL_GL;
    float* ge = sm + SL_GE;
    float* z4 = sm + SL_Z4;
    int tid = threadIdx.x;
    uint32_t rank = blockIdx.x & 1u;
    int b0 = (blockIdx.x >> 1) * RB;
    int col = rank*256 + tid;

    float w[HH];
#pragma unroll
    for (int k = 0; k < HH; k++) w[k] = d_WTh[k*GG + col];
    float wz[ZD];
#pragma unroll
    for (int k = 0; k < ZD; k++) wz[k] = d_WihTh[k*GG + col];
    float bg = d_bh[col];

    for (int i = tid; i < 512; i += 256) h4[i] = 0.f;
    if (tid < RB*ZD) {
        int r = tid >> 4, zi = tid & 15;
        z4[zi*4 + r] = d_zbuf[((size_t)(b0+r)*TT + 0)*ZD + zi];
    }
    float c0 = 0.f, c1 = 0.f;
    __syncthreads();
    CLUSTER_SYNC();
    uint32_t ge_peer = mapa_u32(s2u(ge), rank ^ 1u);

    uint32_t s = 0;
    float znext = 0.f;
    for (int t = 0; t < TT; ++t, ++s) {
        if (t+1 < TT && tid < RB*ZD) {   // prefetch z(t+1)
            int r = tid >> 4, zi = tid & 15;
            znext = d_zbuf[((size_t)(b0+r)*TT + (t+1))*ZD + zi];
        }
        unsigned long long a01a = pk2(bg, bg), a23a = a01a;
        unsigned long long a01b = 0ull, a23b = 0ull;
#pragma unroll
        for (int k = 0; k < ZD; k += 2) {
            ulonglong2 zp0 = *(const ulonglong2*)(z4 + k*4);
            ulonglong2 zp1 = *(const ulonglong2*)(z4 + (k+1)*4);
            unsigned long long wp0 = pk2(wz[k],   wz[k]);
            unsigned long long wp1 = pk2(wz[k+1], wz[k+1]);
            a01a = f2fma(wp0, zp0.x, a01a);
            a23a = f2fma(wp0, zp0.y, a23a);
            a01b = f2fma(wp1, zp1.x, a01b);
            a23b = f2fma(wp1, zp1.y, a23b);
        }
#pragma unroll
        for (int k = 0; k < HH; k += 2) {
            ulonglong2 hp0 = *(const ulonglong2*)(h4 + k*4);
            ulonglong2 hp1 = *(const ulonglong2*)(h4 + (k+1)*4);
            unsigned long long wp0 = pk2(w[k],   w[k]);
            unsigned long long wp1 = pk2(w[k+1], w[k+1]);
            a01a = f2fma(wp0, hp0.x, a01a);
            a23a = f2fma(wp0, hp0.y, a23a);
            a01b = f2fma(wp1, hp1.x, a01b);
            a23b = f2fma(wp1, hp1.y, a23b);
        }
        float g0, g1, g2, g3;
        upk2(add2(a01a, a01b), g0, g1);
        upk2(add2(a23a, a23b), g2, g3);
        int par = s & 1;
        int base = tid*5;
        gl[base+0]=g0; gl[base+1]=g1; gl[base+2]=g2; gl[base+3]=g3;
        uint32_t pa = ge_peer + (uint32_t)(par*1280 + base)*4u;
        stpeer(pa, g0); stpeer(pa+4u, g1); stpeer(pa+8u, g2); stpeer(pa+12u, g3);
        CLUSTER_SYNC();
        // safe to overwrite z4 now: all local gate reads done (cluster barrier passed)
        if (t+1 < TT && tid < RB*ZD) {
            int r = tid >> 4, zi = tid & 15;
            z4[zi*4 + r] = znext;
        }
        const float* gif = rank ? (ge + par*1280) : gl;
        const float* ggo = rank ? gl : (ge + par*1280);
        {
            int r = tid >> 7, hi = tid & 127;
            float i_ = sigf(gif[hi*5+r]);
            float f_ = sigf(gif[(128+hi)*5+r]);
            float g_ = tanhf(ggo[hi*5+r]);
            float o_ = sigf(ggo[(128+hi)*5+r]);
            c0 = f_*c0 + i_*g_;
            float h = o_*tanhf(c0);
            h4[hi*4+r] = h;
            if (!rank) d_hdec[((size_t)(b0+r)*TT + t)*HH + hi] = h;
        }
        {
            int u = tid + 256, r = u >> 7, hi = u & 127;
            float i_ = sigf(gif[hi*5+r]);
            float f_ = sigf(gif[(128+hi)*5+r]);
            float g_ = tanhf(ggo[hi*5+r]);
            float o_ = sigf(ggo[(128+hi)*5+r]);
            c1 = f_*c1 + i_*g_;
            float h = o_*tanhf(c1);
            h4[hi*4+r] = h;
            if (!rank) d_hdec[((size_t)(b0+r)*TT + t)*HH + hi] = h;
        }
        __syncthreads();
    }
}

// ---------------- inference loop ----------------
__global__ void __launch_bounds__(256,1) __cluster_dims__(2,1,1)
inference_kernel(const float* __restrict__ eps,
                 const float* __restrict__ Wm, const float* __restrict__ bm,
                 const float* __restrict__ Wv, const float* __restrict__ bv,
                 float* __restrict__ out_mean, float* __restrict__ out_logvar,
                 float* __restrict__ out_z)
{
    extern __shared__ float sm[];
    float* h4  = sm + SI_H4;
    float* W0R = sm + SI_W0R;
    float* whd = sm + SI_WHD;
    float* hm  = sm + SI_HM;
    float* gl  = sm + SI_GL;
    float* ge  = sm + SI_GE;
    float* mv  = sm + SI_MV;
    float* z4  = sm + SI_Z4;
    int tid = threadIdx.x;
    uint32_t rank = blockIdx.x & 1u;
    int b0 = (blockIdx.x >> 1) * RB;
    int col = rank*256 + tid;

    float w[HH];
#pragma unroll
    for (int k = 0; k < HH; k++) w[k] = d_WTgz[k*GG + col];
    float wz[ZD];
#pragma unroll
    for (int k = 0; k < ZD; k++) wz[k] = d_WihTgz[k*GG + col];
    float bg = d_bgz[col];

    for (int i = tid; i < HH*HH; i += 256) W0R[i] = d_W0RT[i];
    for (int i = tid; i < 32*HH; i += 256) {
        int row = i >> 7, k = i & 127;
        whd[row*132 + k] = (row < 16) ? Wm[row*HH + k] : Wv[(row-16)*HH + k];
    }
    // head constants
    int outv = tid >> 2, kq = tid & 3;
    int rr_h = outv >> 5, head = (outv >> 4) & 1, zi_h = outv & 15;
    float hbias = head ? bv[zi_h] : bm[zi_h];
    // MLP role
    int jm = tid & 127, rrm = tid >> 7;
    int browm = b0 + rank*2 + rrm;

    for (int i = tid; i < 512; i += 256) h4[i] = 0.f;
    float c0 = 0.f, c1 = 0.f;
    __syncthreads();
    CLUSTER_SYNC();
    uint32_t ge_peer = mapa_u32(s2u(ge), rank ^ 1u);
    uint32_t z4_peer = mapa_u32(s2u(z4), rank ^ 1u);

    // prefetches for t=0
    float u0pf = d_u0[((size_t)0*BB + browm)*HH + jm];
    float epf = 0.f;
    int rr_z = tid >> 4, zi_z = tid & 15;
    int brow_z = b0 + rank*2 + rr_z;
    if (tid < 32) epf = eps[((size_t)0*BB + brow_z)*ZD + zi_z];

    uint32_t s = 0;
    for (int t = 0; t < TT; ++t, ++s) {
        float u0c = u0pf;
        float ec = epf;
        if (t+1 < TT) {
            u0pf = d_u0[((size_t)(t+1)*BB + browm)*HH + jm];
            if (tid < 32) epf = eps[((size_t)(t+1)*BB + brow_z)*ZD + zi_z];
        }
        // 1) MLP (all 256 threads: one (row rrm, col jm) each)
        {
            float aa = u0c, ab = 0.f;
            int hidx = rank*2 + rrm;
#pragma unroll
            for (int k = 0; k < HH; k += 2) {
                aa += W0R[k*HH + jm]     * h4[k*4 + hidx];
                ab += W0R[(k+1)*HH + jm] * h4[(k+1)*4 + hidx];
            }
            hm[rrm*HH + jm] = tanhf(aa + ab);
        }
        __syncthreads();
        // 2) heads (64 outputs x 4-way k-split)
        {
            const float* wrow = whd + (head*16 + zi_h)*132 + kq*32;
            const float* hr   = hm + rr_h*HH + kq*32;
            float s0=0.f, s1=0.f, s2=0.f, s3=0.f;
#pragma unroll
            for (int kk = 0; kk < 32; kk += 4) {
                float4 wv4 = *(const float4*)(wrow + kk);
                float4 hv4 = *(const float4*)(hr + kk);
                s0 += wv4.x*hv4.x; s1 += wv4.y*hv4.y;
                s2 += wv4.z*hv4.z; s3 += wv4.w*hv4.w;
            }
            float acc = (s0+s1) + (s2+s3);
            acc += __shfl_xor_sync(0xffffffffu, acc, 1);
            acc += __shfl_xor_sync(0xffffffffu, acc, 2);
            if (kq == 0) mv[outv] = acc + hbias;
        }
        __syncthreads();
        // 3) reparameterize own 2 rows, exchange z
        if (tid < 32) {
            float mn = mv[rr_z*32 + zi_z];
            float lv = mv[rr_z*32 + 16 + zi_z];
            float zv = ec*expf(0.5f*lv) + mn;
            int slot = zi_z*4 + rank*2 + rr_z;
            z4[slot] = zv;
            stpeer(z4_peer + (uint32_t)slot*4u, zv);
            size_t oidx = (size_t)brow_z*ZD*TT + (size_t)zi_z*TT + t;
            out_mean[oidx]   = mn;
            out_logvar[oidx] = lv;
            out_z[oidx]      = zv;
            d_zbuf[((size_t)brow_z*TT + t)*ZD + zi_z] = zv;
        }
        CLUSTER_SYNC();
        // 4) g_z gates
        unsigned long long a01a = pk2(bg, bg), a23a = a01a;
        unsigned long long a01b = 0ull, a23b = 0ull;
#pragma unroll
        for (int k = 0; k < ZD; k += 2) {
            ulonglong2 zp0 = *(const ulonglong2*)(z4 + k*4);
            ulonglong2 zp1 = *(const ulonglong2*)(z4 + (k+1)*4);
            unsigned long long wp0 = pk2(wz[k],   wz[k]);
            unsigned long long wp1 = pk2(wz[k+1], wz[k+1]);
            a01a = f2fma(wp0, zp0.x, a01a);
            a23a = f2fma(wp0, zp0.y, a23a);
            a01b = f2fma(wp1, zp1.x, a01b);
            a23b = f2fma(wp1, zp1.y, a23b);
        }
#pragma unroll
        for (int k = 0; k < HH; k += 2) {
            ulonglong2 hp0 = *(const ulonglong2*)(h4 + k*4);
            ulonglong2 hp1 = *(const ulonglong2*)(h4 + (k+1)*4);
            unsigned long long wp0 = pk2(w[k],   w[k]);
            unsigned long long wp1 = pk2(w[k+1], w[k+1]);
            a01a = f2fma(wp0, hp0.x, a01a);
            a23a = f2fma(wp0, hp0.y, a23a);
            a01b = f2fma(wp1, hp1.x, a01b);
            a23b = f2fma(wp1, hp1.y, a23b);
        }
        float g0, g1, g2, g3;
        upk2(add2(a01a, a01b), g0, g1);
        upk2(add2(a23a, a23b), g2, g3);
        int par = s & 1;
        int base = tid*5;
        gl[base+0]=g0; gl[base+1]=g1; gl[base+2]=g2; gl[base+3]=g3;
        uint32_t pa = ge_peer + (uint32_t)(par*1280 + base)*4u;
        stpeer(pa, g0); stpeer(pa+4u, g1); stpeer(pa+8u, g2); stpeer(pa+12u, g3);
        CLUSTER_SYNC();
        const float* gif = rank ? (ge + par*1280) : gl;
        const float* ggo = rank ? gl : (ge + par*1280);
        {
            int r = tid >> 7, hi = tid & 127;
            float i_ = sigf(gif[hi*5+r]);
            float f_ = sigf(gif[(128+hi)*5+r]);
            float g_ = tanhf(ggo[hi*5+r]);
            float o_ = sigf(ggo[(128+hi)*5+r]);
            c0 = f_*c0 + i_*g_;
            h4[hi*4+r] = o_*tanhf(c0);
        }
        {
            int u = tid + 256, r = u >> 7, hi = u & 127;
            float i_ = sigf(gif[hi*5+r]);
            float f_ = sigf(gif[(128+hi)*5+r]);
            float g_ = tanhf(ggo[hi*5+r]);
            float o_ = sigf(ggo[(128+hi)*5+r]);
            c1 = f_*c1 + i_*g_;
            h4[hi*4+r] = o_*tanhf(c1);
        }
        __syncthreads();
    }
}

// ---------------- host launcher ----------------
extern "C" void kernel_launch(void* const* d_in, const int* in_sizes, int n_in,
                              void* d_out, int out_size)
{
    (void)in_sizes; (void)n_in; (void)out_size;
    const float* x      = (const float*)d_in[0];
    const float* eps    = (const float*)d_in[1];
    const float* Wih_gx = (const float*)d_in[2];
    const float* Whh_gx = (const float*)d_in[3];
    const float* bih_gx = (const float*)d_in[4];
    const float* bhh_gx = (const float*)d_in[5];
    const float* Wih_gz = (const float*)d_in[6];
    const float* Whh_gz = (const float*)d_in[7];
    const float* bih_gz = (const float*)d_in[8];
    const float* bhh_gz = (const float*)d_in[9];
    const float* W0     = (const float*)d_in[10];
    const float* b0     = (const float*)d_in[11];
    const float* Wm     = (const float*)d_in[12];
    const float* bm     = (const float*)d_in[13];
    const float* Wv     = (const float*)d_in[14];
    const float* bv     = (const float*)d_in[15];
    const float* Wih_h  = (const float*)d_in[16];
    const float* Whh_h  = (const float*)d_in[17];
    const float* bih_h  = (const float*)d_in[18];
    const float* bhh_h  = (const float*)d_in[19];
    const float* Wy     = (const float*)d_in[20];
    const float* by     = (const float*)d_in[21];

    float *p_xT, *p_gates, *p_gx, *p_u0, *p_hdec, *p_bgx;
    cudaGetSymbolAddress((void**)&p_xT,    d_xT);
    cudaGetSymbolAddress((void**)&p_gates, d_gates);
    cudaGetSymbolAddress((void**)&p_gx,    d_gx);
    cudaGetSymbolAddress((void**)&p_u0,    d_u0);
    cudaGetSymbolAddress((void**)&p_hdec,  d_hdec);
    cudaGetSymbolAddress((void**)&p_bgx,   d_bgx);

    cudaFuncSetAttribute(lstm_gx_kernel,   cudaFuncAttributeMaxDynamicSharedMemorySize, SMB_LSTM);
    cudaFuncSetAttribute(lstm_dec_kernel,  cudaFuncAttributeMaxDynamicSharedMemorySize, SMB_LSTM);
    cudaFuncSetAttribute(inference_kernel, cudaFuncAttributeMaxDynamicSharedMemorySize, SMB_INF);

    float* out = (float*)d_out;
    const size_t Y_SZ  = (size_t)BB*XD*TT;
    const size_t MV_SZ = (size_t)BB*ZD*TT;

    prep_weights<<<64, 256>>>(Whh_gx, bih_gx, bhh_gx, Wih_gz, Whh_gz, bih_gz, bhh_gz,
                              W0, Wih_h, Whh_h, bih_h, bhh_h);
    transpose_x<<<dim3(XROWS/32, TT/32), 256>>>(x);

    // A) input gates -> [t][gate][256b] layout
    gemm_tn<2><<<dim3(TT*BB/128, GG/64), 256>>>(p_xT, XD, Wih_gx, XD, p_bgx, p_gates,
                                                TT*BB, GG, XD);
    // B) backward LSTM -> gx
    lstm_gx_kernel<<<2*NCLUST, 256, SMB_LSTM>>>();
    // B2) u0 = gx @ W0_left^T + b0  (row-major (t,b,128))
    gemm_tn<0><<<dim3(TT*BB/128, HH/64), 256>>>(p_gx, HH, W0, 2*HH, b0, p_u0,
                                                TT*BB, HH, HH);
    // C) inference loop
    inference_kernel<<<2*NCLUST, 256, SMB_INF>>>(eps, Wm, bm, Wv, bv,
                                                 out + Y_SZ, out + Y_SZ + MV_SZ,
                                                 out + Y_SZ + 2*MV_SZ);
    // E) decoder LSTM -> hdec
    lstm_dec_kernel<<<2*NCLUST, 256, SMB_LSTM>>>();
    // F) y = exp(hdec @ Wy^T + by) -> (B,257,T)
    gemm_tn<1><<<dim3(TT*BB/128, (XD+63)/64), 256>>>(p_hdec, HH, Wy, HH, by, out,
                                                     TT*BB, XD, HH);
}

// round 7
// speedup vs baseline: 3.3337x; 1.0280x over previous
#include <cuda_runtime.h>
#include <math.h>
#include <stdint.h>

#define TT 512
#define BB 256
#define HH 128
#define XD 257
#define ZD 16
#define GG 512         // 4*H
#define RB 4           // batch rows per cluster
#define NCLUST (BB/RB) // 64 clusters -> 128 CTAs
#define XROWS (BB*XD)  // 65792
#define NTH 512        // threads per recurrent CTA

// ---------------- scratch ----------------
__device__ float d_xT[(size_t)TT*BB*XD];      // (t,b,257)
__device__ float d_gates[(size_t)TT*GG*BB];   // [t][512 gatecol][256 b]
__device__ float d_gx[(size_t)TT*BB*HH];      // (t,b,128)
__device__ float d_u0[(size_t)TT*BB*HH];      // (t,b,128)
__device__ float d_zbuf[(size_t)BB*TT*ZD];    // (b,t,16)
__device__ float d_hdec[(size_t)BB*TT*HH];    // (b,t,128)
__device__ float d_WTgx[HH*GG];               // [k][512]
__device__ float d_WTgz[HH*GG];
__device__ float d_WTh [HH*GG];
__device__ float d_W0RT[HH*HH];               // [k][j]
__device__ float d_WihTgz[ZD*GG];             // [k][512]
__device__ float d_WihTh [ZD*GG];
__device__ float d_bgx[GG];
__device__ float d_bgz[GG];
__device__ float d_bh [GG];

// ---- fast activations ----
__device__ __forceinline__ float tanha(float x) {
    float y; asm("tanh.approx.f32 %0, %1;" : "=f"(y) : "f"(x)); return y;
}
__device__ __forceinline__ float sigf(float x) { return fmaf(0.5f, tanha(0.5f*x), 0.5f); }

// ---- f32x2 + cluster helpers ----
__device__ __forceinline__ unsigned long long pk2(float lo, float hi) {
    unsigned long long r; asm("mov.b64 %0, {%1, %2};" : "=l"(r) : "f"(lo), "f"(hi)); return r;
}
__device__ __forceinline__ void upk2(unsigned long long v, float& lo, float& hi) {
    asm("mov.b64 {%0, %1}, %2;" : "=f"(lo), "=f"(hi) : "l"(v));
}
__device__ __forceinline__ unsigned long long f2fma(unsigned long long a, unsigned long long b, unsigned long long c) {
    unsigned long long d; asm("fma.rn.f32x2 %0, %1, %2, %3;" : "=l"(d) : "l"(a), "l"(b), "l"(c)); return d;
}
__device__ __forceinline__ unsigned long long add2(unsigned long long a, unsigned long long b) {
    unsigned long long d; asm("add.rn.f32x2 %0, %1, %2;" : "=l"(d) : "l"(a), "l"(b)); return d;
}
__device__ __forceinline__ uint32_t s2u(const void* p) {
    uint32_t a; asm("{ .reg .u64 t; cvta.to.shared.u64 t, %1; cvt.u32.u64 %0, t; }" : "=r"(a) : "l"(p)); return a;
}
__device__ __forceinline__ uint32_t mapa_u32(uint32_t a, uint32_t rk) {
    uint32_t o; asm("mapa.shared::cluster.u32 %0, %1, %2;" : "=r"(o) : "r"(a), "r"(rk)); return o;
}
__device__ __forceinline__ void stpeer(uint32_t a, float v) {
    asm volatile("st.shared::cluster.f32 [%0], %1;" :: "r"(a), "f"(v) : "memory");
}
#define CLUSTER_SYNC() do { \
    asm volatile("barrier.cluster.arrive.aligned;" ::: "memory"); \
    asm volatile("barrier.cluster.wait.aligned;"   ::: "memory"); } while (0)

// ---------------- weight prep ----------------
__global__ void prep_weights(const float* __restrict__ Whh_gx,
                             const float* __restrict__ bih_gx, const float* __restrict__ bhh_gx,
                             const float* __restrict__ Wih_gz, const float* __restrict__ Whh_gz,
                             const float* __restrict__ bih_gz, const float* __restrict__ bhh_gz,
                             const float* __restrict__ W0,
                             const float* __restrict__ Wih_h, const float* __restrict__ Whh_h,
                             const float* __restrict__ bih_h, const float* __restrict__ bhh_h)
{
    int idx = blockIdx.x*blockDim.x + threadIdx.x;
    int stride = gridDim.x*blockDim.x;
    for (int i = idx; i < GG*HH; i += stride) {
        int j = i / HH, k = i % HH;
        d_WTgx[k*GG + j] = Whh_gx[i];
        d_WTgz[k*GG + j] = Whh_gz[i];
        d_WTh [k*GG + j] = Whh_h [i];
    }
    for (int i = idx; i < HH*HH; i += stride) {
        int j = i / HH, k = i % HH;
        d_W0RT[k*HH + j] = W0[j*(2*HH) + HH + k];
    }
    for (int i = idx; i < GG*ZD; i += stride) {
        int j = i / ZD, k = i % ZD;
        d_WihTgz[k*GG + j] = Wih_gz[i];
        d_WihTh [k*GG + j] = Wih_h [i];
    }
    for (int i = idx; i < GG; i += stride) {
        d_bgx[i] = bih_gx[i] + bhh_gx[i];
        d_bgz[i] = bih_gz[i] + bhh_gz[i];
        d_bh [i] = bih_h [i] + bhh_h [i];
    }
}

// ---------------- x transpose ----------------
__global__ void __launch_bounds__(256) transpose_x(const float* __restrict__ x)
{
    __shared__ float tile[32][33];
    int r0 = blockIdx.x*32;
    int c0 = blockIdx.y*32;
    int tx = threadIdx.x & 31, ty = threadIdx.x >> 5;
#pragma unroll
    for (int i = 0; i < 32; i += 8)
        tile[ty+i][tx] = x[(size_t)(r0+ty+i)*TT + c0 + tx];
    __syncthreads();
#pragma unroll
    for (int i = 0; i < 32; i += 8)
        d_xT[(size_t)(c0+ty+i)*XROWS + r0 + tx] = tile[tx][ty+i];
}

// ---------------- GEMM C = A(MxK) * Bw(NxK)^T + bias, f32x2 packed ----------------
// MODE 0: C[m*N+n]. MODE 1: exp + scatter to (B,257,T). MODE 2: gates layout [t][n][256b].
template<int MODE>
__global__ void __launch_bounds__(256)
gemm_tn(const float* __restrict__ A, int lda,
        const float* __restrict__ Bw, int ldb,
        const float* __restrict__ bias,
        float* __restrict__ C,
        int M, int N, int K)
{
    const int BM = 128, BN = 64, BK = 16;
    __shared__ float As[BK][BM];
    __shared__ unsigned long long Bs2[BK][BN];
    int tid = threadIdx.x;
    int bm = blockIdx.x*BM, bn = blockIdx.y*BN;
    int tm = (tid & 15)*8;
    int tn = (tid >> 4)*4;
    unsigned long long acc[4][4];
#pragma unroll
    for (int p = 0; p < 4; p++)
#pragma unroll
        for (int j = 0; j < 4; j++) acc[p][j] = 0ull;

    int ar = tid >> 1, ac = (tid & 1)*8;
    int br = tid >> 2, bc = (tid & 3)*4;

    for (int kk = 0; kk < K; kk += BK) {
#pragma unroll
        for (int i = 0; i < 8; i++) {
            int k = kk + ac + i;
            As[ac+i][ar] = (k < K) ? A[(size_t)(bm+ar)*lda + k] : 0.f;
        }
#pragma unroll
        for (int i = 0; i < 4; i++) {
            int k = kk + bc + i;
            float bv = (k < K && (bn+br) < N) ? Bw[(size_t)(bn+br)*ldb + k] : 0.f;
            Bs2[bc+i][br] = pk2(bv, bv);
        }
        __syncthreads();
#pragma unroll
        for (int k = 0; k < BK; k++) {
            ulonglong2 aA = *(const ulonglong2*)(&As[k][tm]);
            ulonglong2 aB = *(const ulonglong2*)(&As[k][tm+4]);
            ulonglong2 b01 = *(const ulonglong2*)(&Bs2[k][tn]);
            ulonglong2 b23 = *(const ulonglong2*)(&Bs2[k][tn+2]);
            acc[0][0] = f2fma(aA.x, b01.x, acc[0][0]);
            acc[1][0] = f2fma(aA.y, b01.x, acc[1][0]);
            acc[2][0] = f2fma(aB.x, b01.x, acc[2][0]);
            acc[3][0] = f2fma(aB.y, b01.x, acc[3][0]);
            acc[0][1] = f2fma(aA.x, b01.y, acc[0][1]);
            acc[1][1] = f2fma(aA.y, b01.y, acc[1][1]);
            acc[2][1] = f2fma(aB.x, b01.y, acc[2][1]);
            acc[3][1] = f2fma(aB.y, b01.y, acc[3][1]);
            acc[0][2] = f2fma(aA.x, b23.x, acc[0][2]);
            acc[1][2] = f2fma(aA.y, b23.x, acc[1][2]);
            acc[2][2] = f2fma(aB.x, b23.x, acc[2][2]);
            acc[3][2] = f2fma(aB.y, b23.x, acc[3][2]);
            acc[0][3] = f2fma(aA.x, b23.y, acc[0][3]);
            acc[1][3] = f2fma(aA.y, b23.y, acc[1][3]);
            acc[2][3] = f2fma(aB.x, b23.y, acc[2][3]);
            acc[3][3] = f2fma(aB.y, b23.y, acc[3][3]);
        }
        __syncthreads();
    }

#pragma unroll
    for (int j = 0; j < 4; j++) {
        int n = bn + tn + j;
        if (n >= N) continue;
        float bi = bias[n];
#pragma unroll
        for (int p = 0; p < 4; p++) {
            float v0, v1; upk2(acc[p][j], v0, v1);
            int m0 = bm + tm + 2*p;
            if (MODE == 0) {
                C[(size_t)m0*N + n]     = v0 + bi;
                C[(size_t)(m0+1)*N + n] = v1 + bi;
            } else if (MODE == 2) {
                int t = m0 >> 8, b = m0 & 255;   // m = t*256 + b; pairs never cross t
                C[((size_t)t*GG + n)*BB + b]     = v0 + bi;
                C[((size_t)t*GG + n)*BB + b + 1] = v1 + bi;
            } else {
                int b = m0 >> 9, t = m0 & 511;
                C[(size_t)b*XD*TT + (size_t)n*TT + t] = __expf(v0 + bi);
                int m1 = m0 + 1;
                b = m1 >> 9; t = m1 & 511;
                C[(size_t)b*XD*TT + (size_t)n*TT + t] = __expf(v1 + bi);
            }
        }
    }
}

// ======== shared layouts (float indices) ========
#define SL_H4    0      // [128][4]
#define SL_PAD   512    // [256] x 16B (k-split partial sums)
#define SL_GL    1536   // [256*5]
#define SL_GE    2816   // [2][256*5]
#define SL_Z4    5376   // [16][4]
#define SL_TOT   5440
#define SMB_LSTM (SL_TOT*4)

#define SI_H4    0      // [128][4]
#define SI_PAD   512    // [256] x 16B
#define SI_W0R   1536   // [128][128]
#define SI_WHD   17920  // [32][132]
#define SI_HM    22144  // [2][128]
#define SI_GL    22400  // [256*5]
#define SI_GE    23680  // [2][256*5]
#define SI_MV    26240  // [64]
#define SI_Z4    26304  // [16][4]
#define SI_TOT   26368
#define SMB_INF  (SI_TOT*4)

// ---------------- backward LSTM over precomputed gates -> gx ----------------
__global__ void __launch_bounds__(NTH,1) __cluster_dims__(2,1,1)
lstm_gx_kernel()
{
    extern __shared__ float sm[];
    float* h4  = sm + SL_H4;
    float* pad = sm + SL_PAD;
    float* gl  = sm + SL_GL;
    float* ge  = sm + SL_GE;
    int tid = threadIdx.x;
    int j   = tid & 255;   // gate col within this CTA's half
    int kh  = tid >> 8;    // k-half owner
    uint32_t rank = blockIdx.x & 1u;
    int b0 = (blockIdx.x >> 1) * RB;
    int col = rank*256 + j;

    // this thread's 64 recurrent weights (k = kh*64 .. kh*64+63)
    float w[64];
#pragma unroll
    for (int k = 0; k < 64; k++) w[k] = d_WTgx[(kh*64 + k)*GG + col];

    for (int i = tid; i < 512; i += NTH) h4[i] = 0.f;
    float c_ = 0.f;   // cell state for unit (r=tid>>7, hi=tid&127)
    __syncthreads();
    CLUSTER_SYNC();
    uint32_t ge_peer = mapa_u32(s2u(ge), rank ^ 1u);

    float4 pg = make_float4(0.f,0.f,0.f,0.f);
    if (kh == 0) pg = *(const float4*)(d_gates + ((size_t)(TT-1)*GG + col)*BB + b0);
    uint32_t s = 0;
    for (int t = TT-1; t >= 0; --t, ++s) {
        float4 cur = pg;
        if (t > 0 && kh == 0)
            pg = *(const float4*)(d_gates + ((size_t)(t-1)*GG + col)*BB + b0);
        unsigned long long a01a = (kh==0) ? pk2(cur.x, cur.y) : 0ull;
        unsigned long long a23a = (kh==0) ? pk2(cur.z, cur.w) : 0ull;
        unsigned long long a01b = 0ull, a23b = 0ull;
        const float* hbase = h4 + kh*256;   // kh*64 ks * 4
#pragma unroll
        for (int k = 0; k < 64; k += 2) {
            ulonglong2 hp0 = *(const ulonglong2*)(hbase + k*4);
            ulonglong2 hp1 = *(const ulonglong2*)(hbase + (k+1)*4);
            unsigned long long wp0 = pk2(w[k],   w[k]);
            unsigned long long wp1 = pk2(w[k+1], w[k+1]);
            a01a = f2fma(wp0, hp0.x, a01a);
            a23a = f2fma(wp0, hp0.y, a23a);
            a01b = f2fma(wp1, hp1.x, a01b);
            a23b = f2fma(wp1, hp1.y, a23b);
        }
        unsigned long long a01 = add2(a01a, a01b), a23 = add2(a23a, a23b);
        if (kh == 1) *(ulonglong2*)(pad + j*4) = make_ulonglong2(a01, a23);
        __syncthreads();
        int par = s & 1;
        if (kh == 0) {
            ulonglong2 pp = *(const ulonglong2*)(pad + j*4);
            a01 = add2(a01, pp.x);
            a23 = add2(a23, pp.y);
            float g0, g1, g2, g3;
            upk2(a01, g0, g1); upk2(a23, g2, g3);
            int base = j*5;
            gl[base+0]=g0; gl[base+1]=g1; gl[base+2]=g2; gl[base+3]=g3;
            uint32_t pa = ge_peer + (uint32_t)(par*1280 + base)*4u;
            stpeer(pa, g0); stpeer(pa+4u, g1); stpeer(pa+8u, g2); stpeer(pa+12u, g3);
        }
        CLUSTER_SYNC();
        const float* gif = rank ? (ge + par*1280) : gl;
        const float* ggo = rank ? gl : (ge + par*1280);
        {
            int r = tid >> 7, hi = tid & 127;
            float i_ = sigf(gif[hi*5+r]);
            float f_ = sigf(gif[(128+hi)*5+r]);
            float g_ = tanha(ggo[hi*5+r]);
            float o_ = sigf(ggo[(128+hi)*5+r]);
            c_ = f_*c_ + i_*g_;
            float h = o_*tanha(c_);
            h4[hi*4+r] = h;
            if (!rank) d_gx[((size_t)t*BB + b0 + r)*HH + hi] = h;
        }
        __syncthreads();
    }
}

// ---------------- decoder LSTM over z -> hdec ----------------
__global__ void __launch_bounds__(NTH,1) __cluster_dims__(2,1,1)
lstm_dec_kernel()
{
    extern __shared__ float sm[];
    float* h4  = sm + SL_H4;
    float* pad = sm + SL_PAD;
    float* gl  = sm + SL_GL;
    float* ge  = sm + SL_GE;
    float* z4  = sm + SL_Z4;
    int tid = threadIdx.x;
    int j   = tid & 255;
    int kh  = tid >> 8;
    uint32_t rank = blockIdx.x & 1u;
    int b0 = (blockIdx.x >> 1) * RB;
    int col = rank*256 + j;

    float w[64];
#pragma unroll
    for (int k = 0; k < 64; k++) w[k] = d_WTh[(kh*64 + k)*GG + col];
    float wz[ZD];
#pragma unroll
    for (int k = 0; k < ZD; k++) wz[k] = d_WihTh[k*GG + col];
    float bg = d_bh[col];

    for (int i = tid; i < 512; i += NTH) h4[i] = 0.f;
    if (tid < RB*ZD) {
        int r = tid >> 4, zi = tid & 15;
        z4[zi*4 + r] = d_zbuf[((size_t)(b0+r)*TT + 0)*ZD + zi];
    }
    float c_ = 0.f;
    __syncthreads();
    CLUSTER_SYNC();
    uint32_t ge_peer = mapa_u32(s2u(ge), rank ^ 1u);

    uint32_t s = 0;
    float znext = 0.f;
    for (int t = 0; t < TT; ++t, ++s) {
        if (t+1 < TT && tid < RB*ZD) {
            int r = tid >> 4, zi = tid & 15;
            znext = d_zbuf[((size_t)(b0+r)*TT + (t+1))*ZD + zi];
        }
        unsigned long long a01a = 0ull, a23a = 0ull, a01b = 0ull, a23b = 0ull;
        if (kh == 0) {
            a01a = pk2(bg, bg); a23a = a01a;
#pragma unroll
            for (int k = 0; k < ZD; k += 2) {
                ulonglong2 zp0 = *(const ulonglong2*)(z4 + k*4);
                ulonglong2 zp1 = *(const ulonglong2*)(z4 + (k+1)*4);
                unsigned long long wp0 = pk2(wz[k],   wz[k]);
                unsigned long long wp1 = pk2(wz[k+1], wz[k+1]);
                a01a = f2fma(wp0, zp0.x, a01a);
                a23a = f2fma(wp0, zp0.y, a23a);
                a01b = f2fma(wp1, zp1.x, a01b);
                a23b = f2fma(wp1, zp1.y, a23b);
            }
        }
        const float* hbase = h4 + kh*256;
#pragma unroll
        for (int k = 0; k < 64; k += 2) {
            ulonglong2 hp0 = *(const ulonglong2*)(hbase + k*4);
            ulonglong2 hp1 = *(const ulonglong2*)(hbase + (k+1)*4);
            unsigned long long wp0 = pk2(w[k],   w[k]);
            unsigned long long wp1 = pk2(w[k+1], w[k+1]);
            a01a = f2fma(wp0, hp0.x, a01a);
            a23a = f2fma(wp0, hp0.y, a23a);
            a01b = f2fma(wp1, hp1.x, a01b);
            a23b = f2fma(wp1, hp1.y, a23b);
        }
        unsigned long long a01 = add2(a01a, a01b), a23 = add2(a23a, a23b);
        if (kh == 1) *(ulonglong2*)(pad + j*4) = make_ulonglong2(a01, a23);
        __syncthreads();
        int par = s & 1;
        if (kh == 0) {
            ulonglong2 pp = *(const ulonglong2*)(pad + j*4);
            a01 = add2(a01, pp.x);
            a23 = add2(a23, pp.y);
            float g0, g1, g2, g3;
            upk2(a01, g0, g1); upk2(a23, g2, g3);
            int base = j*5;
            gl[base+0]=g0; gl[base+1]=g1; gl[base+2]=g2; gl[base+3]=g3;
            uint32_t pa = ge_peer + (uint32_t)(par*1280 + base)*4u;
            stpeer(pa, g0); stpeer(pa+4u, g1); stpeer(pa+8u, g2); stpeer(pa+12u, g3);
        }
        CLUSTER_SYNC();
        if (t+1 < TT && tid < RB*ZD) {   // gate reads of z done; safe to overwrite
            int r = tid >> 4, zi = tid & 15;
            z4[zi*4 + r] = znext;
        }
        const float* gif = rank ? (ge + par*1280) : gl;
        const float* ggo = rank ? gl : (ge + par*1280);
        {
            int r = tid >> 7, hi = tid & 127;
            float i_ = sigf(gif[hi*5+r]);
            float f_ = sigf(gif[(128+hi)*5+r]);
            float g_ = tanha(ggo[hi*5+r]);
            float o_ = sigf(ggo[(128+hi)*5+r]);
            c_ = f_*c_ + i_*g_;
            float h = o_*tanha(c_);
            h4[hi*4+r] = h;
            if (!rank) d_hdec[((size_t)(b0+r)*TT + t)*HH + hi] = h;
        }
        __syncthreads();
    }
}

// ---------------- inference loop ----------------
__global__ void __launch_bounds__(NTH,1) __cluster_dims__(2,1,1)
inference_kernel(const float* __restrict__ eps,
                 const float* __restrict__ Wm, const float* __restrict__ bm,
                 const float* __restrict__ Wv, const float* __restrict__ bv,
                 float* __restrict__ out_mean, float* __restrict__ out_logvar,
                 float* __restrict__ out_z)
{
    extern __shared__ float sm[];
    float* h4  = sm + SI_H4;
    float* pad = sm + SI_PAD;
    float* W0R = sm + SI_W0R;
    float* whd = sm + SI_WHD;
    float* hm  = sm + SI_HM;
    float* gl  = sm + SI_GL;
    float* ge  = sm + SI_GE;
    float* mv  = sm + SI_MV;
    float* z4  = sm + SI_Z4;
    int tid = threadIdx.x;
    int j   = tid & 255;
    int kh  = tid >> 8;
    uint32_t rank = blockIdx.x & 1u;
    int b0 = (blockIdx.x >> 1) * RB;
    int col = rank*256 + j;

    float w[64];
#pragma unroll
    for (int k = 0; k < 64; k++) w[k] = d_WTgz[(kh*64 + k)*GG + col];
    float wz[ZD];
#pragma unroll
    for (int k = 0; k < ZD; k++) wz[k] = d_WihTgz[k*GG + col];
    float bg = d_bgz[col];

    for (int i = tid; i < HH*HH; i += NTH) W0R[i] = d_W0RT[i];
    for (int i = tid; i < 32*HH; i += NTH) {
        int row = i >> 7, k = i & 127;
        whd[row*132 + k] = (row < 16) ? Wm[row*HH + k] : Wv[(row-16)*HH + k];
    }
    // heads role: 64 outputs x 8-way k-split
    int outv = tid >> 3, kq = tid & 7;
    int rr_h = (outv >> 5) & 1, head = (outv >> 4) & 1, zi_h = outv & 15;
    float hbias = head ? bv[zi_h] : bm[zi_h];
    // MLP role: out = tid&255 -> (row rrm, col jm), kh = k-half
    int jm = tid & 127, rrm = (tid >> 7) & 1;
    int browm = b0 + rank*2 + rrm;
    int hidxm = rank*2 + rrm;
    // reparam role
    int rr_z = (tid >> 4) & 1, zi_z = tid & 15;
    int brow_z = b0 + rank*2 + rr_z;

    for (int i = tid; i < 512; i += NTH) h4[i] = 0.f;
    float c_ = 0.f;
    __syncthreads();
    CLUSTER_SYNC();
    uint32_t ge_peer = mapa_u32(s2u(ge), rank ^ 1u);
    uint32_t z4_peer = mapa_u32(s2u(z4), rank ^ 1u);

    // prefetches for t=0 (kh==0 threads own MLP input; tid<32 own eps)
    float u0pf = 0.f, epf = 0.f;
    if (kh == 0) u0pf = d_u0[((size_t)0*BB + browm)*HH + jm];
    if (tid < 32) epf = eps[((size_t)0*BB + brow_z)*ZD + zi_z];

    uint32_t s = 0;
    for (int t = 0; t < TT; ++t, ++s) {
        float u0c = u0pf;
        float ec = epf;
        if (t+1 < TT) {
            if (kh == 0) u0pf = d_u0[((size_t)(t+1)*BB + browm)*HH + jm];
            if (tid < 32) epf = eps[((size_t)(t+1)*BB + brow_z)*ZD + zi_z];
        }
        // 1) MLP partial: out (rrm,jm), k-half kh
        {
            float aa = (kh == 0) ? u0c : 0.f, ab = 0.f;
            const float* wb = W0R + kh*64*HH;
            const float* hb = h4 + kh*256;
#pragma unroll
            for (int k = 0; k < 64; k += 2) {
                aa += wb[k*HH + jm]     * hb[k*4 + hidxm];
                ab += wb[(k+1)*HH + jm] * hb[(k+1)*4 + hidxm];
            }
            float acc = aa + ab;
            if (kh == 1) pad[(rrm*128 + jm)] = acc;
            __syncthreads();
            if (kh == 0) {
                acc += pad[rrm*128 + jm];
                hm[rrm*HH + jm] = tanha(acc);
            }
        }
        __syncthreads();
        // 2) heads: 64 outputs x 8-way k-split
        {
            const float* wrow = whd + (head*16 + zi_h)*132 + kq*16;
            const float* hr   = hm + rr_h*HH + kq*16;
            float s0=0.f, s1=0.f, s2=0.f, s3=0.f;
#pragma unroll
            for (int kk = 0; kk < 16; kk += 4) {
                float4 wv4 = *(const float4*)(wrow + kk);
                float4 hv4 = *(const float4*)(hr + kk);
                s0 += wv4.x*hv4.x; s1 += wv4.y*hv4.y;
                s2 += wv4.z*hv4.z; s3 += wv4.w*hv4.w;
            }
            float acc = (s0+s1) + (s2+s3);
            acc += __shfl_xor_sync(0xffffffffu, acc, 1);
            acc += __shfl_xor_sync(0xffffffffu, acc, 2);
            acc += __shfl_xor_sync(0xffffffffu, acc, 4);
            if (kq == 0) mv[outv] = acc + hbias;
        }
        __syncthreads();
        // 3) reparameterize own 2 rows, exchange z
        if (tid < 32) {
            float mn = mv[rr_z*32 + zi_z];
            float lv = mv[rr_z*32 + 16 + zi_z];
            float zv = ec*expf(0.5f*lv) + mn;
            int slot = zi_z*4 + rank*2 + rr_z;
            z4[slot] = zv;
            stpeer(z4_peer + (uint32_t)slot*4u, zv);
            size_t oidx = (size_t)brow_z*ZD*TT + (size_t)zi_z*TT + t;
            out_mean[oidx]   = mn;
            out_logvar[oidx] = lv;
            out_z[oidx]      = zv;
            d_zbuf[((size_t)brow_z*TT + t)*ZD + zi_z] = zv;
        }
        CLUSTER_SYNC();
        // 4) g_z gates: k-split
        unsigned long long a01a = 0ull, a23a = 0ull, a01b = 0ull, a23b = 0ull;
        if (kh == 0) {
            a01a = pk2(bg, bg); a23a = a01a;
#pragma unroll
            for (int k = 0; k < ZD; k += 2) {
                ulonglong2 zp0 = *(const ulonglong2*)(z4 + k*4);
                ulonglong2 zp1 = *(const ulonglong2*)(z4 + (k+1)*4);
                unsigned long long wp0 = pk2(wz[k],   wz[k]);
                unsigned long long wp1 = pk2(wz[k+1], wz[k+1]);
                a01a = f2fma(wp0, zp0.x, a01a);
                a23a = f2fma(wp0, zp0.y, a23a);
                a01b = f2fma(wp1, zp1.x, a01b);
                a23b = f2fma(wp1, zp1.y, a23b);
            }
        }
        const float* hbase = h4 + kh*256;
#pragma unroll
        for (int k = 0; k < 64; k += 2) {
            ulonglong2 hp0 = *(const ulonglong2*)(hbase + k*4);
            ulonglong2 hp1 = *(const ulonglong2*)(hbase + (k+1)*4);
            unsigned long long wp0 = pk2(w[k],   w[k]);
            unsigned long long wp1 = pk2(w[k+1], w[k+1]);
            a01a = f2fma(wp0, hp0.x, a01a);
            a23a = f2fma(wp0, hp0.y, a23a);
            a01b = f2fma(wp1, hp1.x, a01b);
            a23b = f2fma(wp1, hp1.y, a23b);
        }
        unsigned long long a01 = add2(a01a, a01b), a23 = add2(a23a, a23b);
        if (kh == 1) *(ulonglong2*)(pad + j*4) = make_ulonglong2(a01, a23);
        __syncthreads();
        int par = s & 1;
        if (kh == 0) {
            ulonglong2 pp = *(const ulonglong2*)(pad + j*4);
            a01 = add2(a01, pp.x);
            a23 = add2(a23, pp.y);
            float g0, g1, g2, g3;
            upk2(a01, g0, g1); upk2(a23, g2, g3);
            int base = j*5;
            gl[base+0]=g0; gl[base+1]=g1; gl[base+2]=g2; gl[base+3]=g3;
            uint32_t pa = ge_peer + (uint32_t)(par*1280 + base)*4u;
            stpeer(pa, g0); stpeer(pa+4u, g1); stpeer(pa+8u, g2); stpeer(pa+12u, g3);
        }
        CLUSTER_SYNC();
        const float* gif = rank ? (ge + par*1280) : gl;
        const float* ggo = rank ? gl : (ge + par*1280);
        {
            int r = tid >> 7, hi = tid & 127;
            float i_ = sigf(gif[hi*5+r]);
            float f_ = sigf(gif[(128+hi)*5+r]);
            float g_ = tanha(ggo[hi*5+r]);
            float o_ = sigf(ggo[(128+hi)*5+r]);
            c_ = f_*c_ + i_*g_;
            h4[hi*4+r] = o_*tanha(c_);
        }
        __syncthreads();
    }
}

// ---------------- host launcher ----------------
extern "C" void kernel_launch(void* const* d_in, const int* in_sizes, int n_in,
                              void* d_out, int out_size)
{
    (void)in_sizes; (void)n_in; (void)out_size;
    const float* x      = (const float*)d_in[0];
    const float* eps    = (const float*)d_in[1];
    const float* Wih_gx = (const float*)d_in[2];
    const float* Whh_gx = (const float*)d_in[3];
    const float* bih_gx = (const float*)d_in[4];
    const float* bhh_gx = (const float*)d_in[5];
    const float* Wih_gz = (const float*)d_in[6];
    const float* Whh_gz = (const float*)d_in[7];
    const float* bih_gz = (const float*)d_in[8];
    const float* bhh_gz = (const float*)d_in[9];
    const float* W0     = (const float*)d_in[10];
    const float* b0     = (const float*)d_in[11];
    const float* Wm     = (const float*)d_in[12];
    const float* bm     = (const float*)d_in[13];
    const float* Wv     = (const float*)d_in[14];
    const float* bv     = (const float*)d_in[15];
    const float* Wih_h  = (const float*)d_in[16];
    const float* Whh_h  = (const float*)d_in[17];
    const float* bih_h  = (const float*)d_in[18];
    const float* bhh_h  = (const float*)d_in[19];
    const float* Wy     = (const float*)d_in[20];
    const float* by     = (const float*)d_in[21];

    float *p_xT, *p_gates, *p_gx, *p_u0, *p_hdec, *p_bgx;
    cudaGetSymbolAddress((void**)&p_xT,    d_xT);
    cudaGetSymbolAddress((void**)&p_gates, d_gates);
    cudaGetSymbolAddress((void**)&p_gx,    d_gx);
    cudaGetSymbolAddress((void**)&p_u0,    d_u0);
    cudaGetSymbolAddress((void**)&p_hdec,  d_hdec);
    cudaGetSymbolAddress((void**)&p_bgx,   d_bgx);

    cudaFuncSetAttribute(lstm_gx_kernel,   cudaFuncAttributeMaxDynamicSharedMemorySize, SMB_LSTM);
    cudaFuncSetAttribute(lstm_dec_kernel,  cudaFuncAttributeMaxDynamicSharedMemorySize, SMB_LSTM);
    cudaFuncSetAttribute(inference_kernel, cudaFuncAttributeMaxDynamicSharedMemorySize, SMB_INF);

    float* out = (float*)d_out;
    const size_t Y_SZ  = (size_t)BB*XD*TT;
    const size_t MV_SZ = (size_t)BB*ZD*TT;

    prep_weights<<<64, 256>>>(Whh_gx, bih_gx, bhh_gx, Wih_gz, Whh_gz, bih_gz, bhh_gz,
                              W0, Wih_h, Whh_h, bih_h, bhh_h);
    transpose_x<<<dim3(XROWS/32, TT/32), 256>>>(x);

    // A) input gates -> [t][gate][256b] layout
    gemm_tn<2><<<dim3(TT*BB/128, GG/64), 256>>>(p_xT, XD, Wih_gx, XD, p_bgx, p_gates,
                                                TT*BB, GG, XD);
    // B) backward LSTM -> gx
    lstm_gx_kernel<<<2*NCLUST, NTH, SMB_LSTM>>>();
    // B2) u0 = gx @ W0_left^T + b0  (row-major (t,b,128))
    gemm_tn<0><<<dim3(TT*BB/128, HH/64), 256>>>(p_gx, HH, W0, 2*HH, b0, p_u0,
                                                TT*BB, HH, HH);
    // C) inference loop
    inference_kernel<<<2*NCLUST, NTH, SMB_INF>>>(eps, Wm, bm, Wv, bv,
                                                 out + Y_SZ, out + Y_SZ + MV_SZ,
                                                 out + Y_SZ + 2*MV_SZ);
    // E) decoder LSTM -> hdec
    lstm_dec_kernel<<<2*NCLUST, NTH, SMB_LSTM>>>();
    // F) y = exp(hdec @ Wy^T + by) -> (B,257,T)
    gemm_tn<1><<<dim3(TT*BB/128, (XD+63)/64), 256>>>(p_hdec, HH, Wy, HH, by, out,
                                                     TT*BB, XD, HH);
}

// round 8
// speedup vs baseline: 3.3393x; 1.0017x over previous
#include <cuda_runtime.h>
#include <math.h>
#include <stdint.h>

#define TT 512
#define BB 256
#define HH 128
#define XD 257
#define ZD 16
#define GG 512         // 4*H
#define RB 4           // batch rows per cluster
#define NCLUST (BB/RB) // 64 clusters -> 128 CTAs
#define XROWS (BB*XD)  // 65792
#define NTH 512        // threads per recurrent CTA

// ---------------- scratch ----------------
__device__ float d_xT[(size_t)TT*BB*XD];      // (t,b,257)
__device__ float d_gates[(size_t)TT*GG*BB];   // [t][512 gatecol][256 b]
__device__ float d_gx[(size_t)TT*BB*HH];      // (t,b,128)
__device__ float d_u0[(size_t)TT*BB*HH];      // (t,b,128)
__device__ float d_zbuf[(size_t)BB*TT*ZD];    // (b,t,16)
__device__ float d_hdec[(size_t)BB*TT*HH];    // (b,t,128)
__device__ float d_WTgx[HH*GG];               // [k][512]
__device__ float d_WTgz[HH*GG];
__device__ float d_WTh [HH*GG];
__device__ float d_W0RT[HH*HH];               // [k][j]
__device__ float d_WihTgz[ZD*GG];             // [k][512]
__device__ float d_WihTh [ZD*GG];
__device__ float d_bgx[GG];
__device__ float d_bgz[GG];
__device__ float d_bh [GG];

// ---- fast activations ----
__device__ __forceinline__ float tanha(float x) {
    float y; asm("tanh.approx.f32 %0, %1;" : "=f"(y) : "f"(x)); return y;
}
__device__ __forceinline__ float sigf(float x) { return fmaf(0.5f, tanha(0.5f*x), 0.5f); }

// ---- f32x2 + cluster helpers ----
__device__ __forceinline__ unsigned long long pk2(float lo, float hi) {
    unsigned long long r; asm("mov.b64 %0, {%1, %2};" : "=l"(r) : "f"(lo), "f"(hi)); return r;
}
__device__ __forceinline__ void upk2(unsigned long long v, float& lo, float& hi) {
    asm("mov.b64 {%0, %1}, %2;" : "=f"(lo), "=f"(hi) : "l"(v));
}
__device__ __forceinline__ unsigned long long f2fma(unsigned long long a, unsigned long long b, unsigned long long c) {
    unsigned long long d; asm("fma.rn.f32x2 %0, %1, %2, %3;" : "=l"(d) : "l"(a), "l"(b), "l"(c)); return d;
}
__device__ __forceinline__ unsigned long long add2(unsigned long long a, unsigned long long b) {
    unsigned long long d; asm("add.rn.f32x2 %0, %1, %2;" : "=l"(d) : "l"(a), "l"(b)); return d;
}
__device__ __forceinline__ uint32_t s2u(const void* p) {
    uint32_t a; asm("{ .reg .u64 t; cvta.to.shared.u64 t, %1; cvt.u32.u64 %0, t; }" : "=r"(a) : "l"(p)); return a;
}
__device__ __forceinline__ uint32_t mapa_u32(uint32_t a, uint32_t rk) {
    uint32_t o; asm("mapa.shared::cluster.u32 %0, %1, %2;" : "=r"(o) : "r"(a), "r"(rk)); return o;
}
__device__ __forceinline__ void stpeer(uint32_t a, float v) {
    asm volatile("st.shared::cluster.f32 [%0], %1;" :: "r"(a), "f"(v) : "memory");
}
#define CLUSTER_SYNC() do { \
    asm volatile("barrier.cluster.arrive.aligned;" ::: "memory"); \
    asm volatile("barrier.cluster.wait.aligned;"   ::: "memory"); } while (0)

// ---------------- weight prep ----------------
__global__ void prep_weights(const float* __restrict__ Whh_gx,
                             const float* __restrict__ bih_gx, const float* __restrict__ bhh_gx,
                             const float* __restrict__ Wih_gz, const float* __restrict__ Whh_gz,
                             const float* __restrict__ bih_gz, const float* __restrict__ bhh_gz,
                             const float* __restrict__ W0,
                             const float* __restrict__ Wih_h, const float* __restrict__ Whh_h,
                             const float* __restrict__ bih_h, const float* __restrict__ bhh_h)
{
    int idx = blockIdx.x*blockDim.x + threadIdx.x;
    int stride = gridDim.x*blockDim.x;
    for (int i = idx; i < GG*HH; i += stride) {
        int j = i / HH, k = i % HH;
        d_WTgx[k*GG + j] = Whh_gx[i];
        d_WTgz[k*GG + j] = Whh_gz[i];
        d_WTh [k*GG + j] = Whh_h [i];
    }
    for (int i = idx; i < HH*HH; i += stride) {
        int j = i / HH, k = i % HH;
        d_W0RT[k*HH + j] = W0[j*(2*HH) + HH + k];
    }
    for (int i = idx; i < GG*ZD; i += stride) {
        int j = i / ZD, k = i % ZD;
        d_WihTgz[k*GG + j] = Wih_gz[i];
        d_WihTh [k*GG + j] = Wih_h [i];
    }
    for (int i = idx; i < GG; i += stride) {
        d_bgx[i] = bih_gx[i] + bhh_gx[i];
        d_bgz[i] = bih_gz[i] + bhh_gz[i];
        d_bh [i] = bih_h [i] + bhh_h [i];
    }
}

// ---------------- x transpose ----------------
__global__ void __launch_bounds__(256) transpose_x(const float* __restrict__ x)
{
    __shared__ float tile[32][33];
    int r0 = blockIdx.x*32;
    int c0 = blockIdx.y*32;
    int tx = threadIdx.x & 31, ty = threadIdx.x >> 5;
#pragma unroll
    for (int i = 0; i < 32; i += 8)
        tile[ty+i][tx] = x[(size_t)(r0+ty+i)*TT + c0 + tx];
    __syncthreads();
#pragma unroll
    for (int i = 0; i < 32; i += 8)
        d_xT[(size_t)(c0+ty+i)*XROWS + r0 + tx] = tile[tx][ty+i];
}

// ---------------- GEMM C = A(MxK) * Bw(NxK)^T + bias, f32x2 packed ----------------
// MODE 0: C[m*N+n]. MODE 1: exp + scatter to (B,257,T). MODE 2: gates layout [t][n][256b].
template<int MODE>
__global__ void __launch_bounds__(256)
gemm_tn(const float* __restrict__ A, int lda,
        const float* __restrict__ Bw, int ldb,
        const float* __restrict__ bias,
        float* __restrict__ C,
        int M, int N, int K)
{
    const int BM = 128, BN = 64, BK = 16;
    __shared__ float As[BK][BM];
    __shared__ unsigned long long Bs2[BK][BN];
    int tid = threadIdx.x;
    int bm = blockIdx.x*BM, bn = blockIdx.y*BN;
    int tm = (tid & 15)*8;
    int tn = (tid >> 4)*4;
    unsigned long long acc[4][4];
#pragma unroll
    for (int p = 0; p < 4; p++)
#pragma unroll
        for (int j = 0; j < 4; j++) acc[p][j] = 0ull;

    int ar = tid >> 1, ac = (tid & 1)*8;
    int br = tid >> 2, bc = (tid & 3)*4;

    for (int kk = 0; kk < K; kk += BK) {
#pragma unroll
        for (int i = 0; i < 8; i++) {
            int k = kk + ac + i;
            As[ac+i][ar] = (k < K) ? A[(size_t)(bm+ar)*lda + k] : 0.f;
        }
#pragma unroll
        for (int i = 0; i < 4; i++) {
            int k = kk + bc + i;
            float bv = (k < K && (bn+br) < N) ? Bw[(size_t)(bn+br)*ldb + k] : 0.f;
            Bs2[bc+i][br] = pk2(bv, bv);
        }
        __syncthreads();
#pragma unroll
        for (int k = 0; k < BK; k++) {
            ulonglong2 aA = *(const ulonglong2*)(&As[k][tm]);
            ulonglong2 aB = *(const ulonglong2*)(&As[k][tm+4]);
            ulonglong2 b01 = *(const ulonglong2*)(&Bs2[k][tn]);
            ulonglong2 b23 = *(const ulonglong2*)(&Bs2[k][tn+2]);
            acc[0][0] = f2fma(aA.x, b01.x, acc[0][0]);
            acc[1][0] = f2fma(aA.y, b01.x, acc[1][0]);
            acc[2][0] = f2fma(aB.x, b01.x, acc[2][0]);
            acc[3][0] = f2fma(aB.y, b01.x, acc[3][0]);
            acc[0][1] = f2fma(aA.x, b01.y, acc[0][1]);
            acc[1][1] = f2fma(aA.y, b01.y, acc[1][1]);
            acc[2][1] = f2fma(aB.x, b01.y, acc[2][1]);
            acc[3][1] = f2fma(aB.y, b01.y, acc[3][1]);
            acc[0][2] = f2fma(aA.x, b23.x, acc[0][2]);
            acc[1][2] = f2fma(aA.y, b23.x, acc[1][2]);
            acc[2][2] = f2fma(aB.x, b23.x, acc[2][2]);
            acc[3][2] = f2fma(aB.y, b23.x, acc[3][2]);
            acc[0][3] = f2fma(aA.x, b23.y, acc[0][3]);
            acc[1][3] = f2fma(aA.y, b23.y, acc[1][3]);
            acc[2][3] = f2fma(aB.x, b23.y, acc[2][3]);
            acc[3][3] = f2fma(aB.y, b23.y, acc[3][3]);
        }
        __syncthreads();
    }

#pragma unroll
    for (int j = 0; j < 4; j++) {
        int n = bn + tn + j;
        if (n >= N) continue;
        float bi = bias[n];
#pragma unroll
        for (int p = 0; p < 4; p++) {
            float v0, v1; upk2(acc[p][j], v0, v1);
            int m0 = bm + tm + 2*p;
            if (MODE == 0) {
                C[(size_t)m0*N + n]     = v0 + bi;
                C[(size_t)(m0+1)*N + n] = v1 + bi;
            } else if (MODE == 2) {
                int t = m0 >> 8, b = m0 & 255;   // m = t*256 + b; pairs never cross t
                C[((size_t)t*GG + n)*BB + b]     = v0 + bi;
                C[((size_t)t*GG + n)*BB + b + 1] = v1 + bi;
            } else {
                int b = m0 >> 9, t = m0 & 511;
                C[(size_t)b*XD*TT + (size_t)n*TT + t] = __expf(v0 + bi);
                int m1 = m0 + 1;
                b = m1 >> 9; t = m1 & 511;
                C[(size_t)b*XD*TT + (size_t)n*TT + t] = __expf(v1 + bi);
            }
        }
    }
}

// ======== shared layouts (float indices) ========
#define SL_H4    0      // [128][4]
#define SL_PAD   512    // [256] x 16B (k-split partial sums)
#define SL_GL    1536   // [256*5]
#define SL_GE    2816   // [2][256*5]
#define SL_Z4    5376   // [16][4]
#define SL_TOT   5440
#define SMB_LSTM (SL_TOT*4)

#define SI_H4    0      // [128][4]
#define SI_PAD   512    // [256] x 16B
#define SI_W0R   1536   // [128][128]
#define SI_WHD   17920  // [32][132]
#define SI_HM    22144  // [2][128]
#define SI_GL    22400  // [256*5]
#define SI_GE    23680  // [2][256*5]
#define SI_MV    26240  // [64]
#define SI_Z4    26304  // [16][4]
#define SI_TOT   26368
#define SMB_INF  (SI_TOT*4)

// ---------------- backward LSTM over precomputed gates -> gx ----------------
__global__ void __launch_bounds__(NTH,1) __cluster_dims__(2,1,1)
lstm_gx_kernel()
{
    extern __shared__ float sm[];
    float* h4  = sm + SL_H4;
    float* pad = sm + SL_PAD;
    float* gl  = sm + SL_GL;
    float* ge  = sm + SL_GE;
    int tid = threadIdx.x;
    int j   = tid & 255;   // gate col within this CTA's half
    int kh  = tid >> 8;    // k-half owner
    uint32_t rank = blockIdx.x & 1u;
    int b0 = (blockIdx.x >> 1) * RB;
    int col = rank*256 + j;

    // this thread's 64 recurrent weights (k = kh*64 .. kh*64+63)
    float w[64];
#pragma unroll
    for (int k = 0; k < 64; k++) w[k] = d_WTgx[(kh*64 + k)*GG + col];

    for (int i = tid; i < 512; i += NTH) h4[i] = 0.f;
    float c_ = 0.f;   // cell state for unit (r=tid>>7, hi=tid&127)
    __syncthreads();
    CLUSTER_SYNC();
    uint32_t ge_peer = mapa_u32(s2u(ge), rank ^ 1u);

    float4 pg = make_float4(0.f,0.f,0.f,0.f);
    if (kh == 0) pg = *(const float4*)(d_gates + ((size_t)(TT-1)*GG + col)*BB + b0);
    uint32_t s = 0;
    for (int t = TT-1; t >= 0; --t, ++s) {
        float4 cur = pg;
        if (t > 0 && kh == 0)
            pg = *(const float4*)(d_gates + ((size_t)(t-1)*GG + col)*BB + b0);
        unsigned long long a01a = (kh==0) ? pk2(cur.x, cur.y) : 0ull;
        unsigned long long a23a = (kh==0) ? pk2(cur.z, cur.w) : 0ull;
        unsigned long long a01b = 0ull, a23b = 0ull;
        const float* hbase = h4 + kh*256;   // kh*64 ks * 4
#pragma unroll
        for (int k = 0; k < 64; k += 2) {
            ulonglong2 hp0 = *(const ulonglong2*)(hbase + k*4);
            ulonglong2 hp1 = *(const ulonglong2*)(hbase + (k+1)*4);
            unsigned long long wp0 = pk2(w[k],   w[k]);
            unsigned long long wp1 = pk2(w[k+1], w[k+1]);
            a01a = f2fma(wp0, hp0.x, a01a);
            a23a = f2fma(wp0, hp0.y, a23a);
            a01b = f2fma(wp1, hp1.x, a01b);
            a23b = f2fma(wp1, hp1.y, a23b);
        }
        unsigned long long a01 = add2(a01a, a01b), a23 = add2(a23a, a23b);
        if (kh == 1) *(ulonglong2*)(pad + j*4) = make_ulonglong2(a01, a23);
        __syncthreads();
        int par = s & 1;
        if (kh == 0) {
            ulonglong2 pp = *(const ulonglong2*)(pad + j*4);
            a01 = add2(a01, pp.x);
            a23 = add2(a23, pp.y);
            float g0, g1, g2, g3;
            upk2(a01, g0, g1); upk2(a23, g2, g3);
            int base = j*5;
            gl[base+0]=g0; gl[base+1]=g1; gl[base+2]=g2; gl[base+3]=g3;
            uint32_t pa = ge_peer + (uint32_t)(par*1280 + base)*4u;
            stpeer(pa, g0); stpeer(pa+4u, g1); stpeer(pa+8u, g2); stpeer(pa+12u, g3);
        }
        CLUSTER_SYNC();
        const float* gif = rank ? (ge + par*1280) : gl;
        const float* ggo = rank ? gl : (ge + par*1280);
        {
            int r = tid >> 7, hi = tid & 127;
            float i_ = sigf(gif[hi*5+r]);
            float f_ = sigf(gif[(128+hi)*5+r]);
            float g_ = tanha(ggo[hi*5+r]);
            float o_ = sigf(ggo[(128+hi)*5+r]);
            c_ = f_*c_ + i_*g_;
            float h = o_*tanha(c_);
            h4[hi*4+r] = h;
            if (!rank) d_gx[((size_t)t*BB + b0 + r)*HH + hi] = h;
        }
        __syncthreads();
    }
}

// ---------------- decoder LSTM over z -> hdec ----------------
__global__ void __launch_bounds__(NTH,1) __cluster_dims__(2,1,1)
lstm_dec_kernel()
{
    extern __shared__ float sm[];
    float* h4  = sm + SL_H4;
    float* pad = sm + SL_PAD;
    float* gl  = sm + SL_GL;
    float* ge  = sm + SL_GE;
    float* z4  = sm + SL_Z4;
    int tid = threadIdx.x;
    int j   = tid & 255;
    int kh  = tid >> 8;
    uint32_t rank = blockIdx.x & 1u;
    int b0 = (blockIdx.x >> 1) * RB;
    int col = rank*256 + j;

    float w[64];
#pragma unroll
    for (int k = 0; k < 64; k++) w[k] = d_WTh[(kh*64 + k)*GG + col];
    float wz[ZD];
#pragma unroll
    for (int k = 0; k < ZD; k++) wz[k] = d_WihTh[k*GG + col];
    float bg = d_bh[col];

    for (int i = tid; i < 512; i += NTH) h4[i] = 0.f;
    if (tid < RB*ZD) {
        int r = tid >> 4, zi = tid & 15;
        z4[zi*4 + r] = d_zbuf[((size_t)(b0+r)*TT + 0)*ZD + zi];
    }
    float c_ = 0.f;
    __syncthreads();
    CLUSTER_SYNC();
    uint32_t ge_peer = mapa_u32(s2u(ge), rank ^ 1u);

    uint32_t s = 0;
    float znext = 0.f;
    for (int t = 0; t < TT; ++t, ++s) {
        if (t+1 < TT && tid < RB*ZD) {
            int r = tid >> 4, zi = tid & 15;
            znext = d_zbuf[((size_t)(b0+r)*TT + (t+1))*ZD + zi];
        }
        unsigned long long a01a = 0ull, a23a = 0ull, a01b = 0ull, a23b = 0ull;
        if (kh == 0) {
            a01a = pk2(bg, bg); a23a = a01a;
#pragma unroll
            for (int k = 0; k < ZD; k += 2) {
                ulonglong2 zp0 = *(const ulonglong2*)(z4 + k*4);
                ulonglong2 zp1 = *(const ulonglong2*)(z4 + (k+1)*4);
                unsigned long long wp0 = pk2(wz[k],   wz[k]);
                unsigned long long wp1 = pk2(wz[k+1], wz[k+1]);
                a01a = f2fma(wp0, zp0.x, a01a);
                a23a = f2fma(wp0, zp0.y, a23a);
                a01b = f2fma(wp1, zp1.x, a01b);
                a23b = f2fma(wp1, zp1.y, a23b);
            }
        }
        const float* hbase = h4 + kh*256;
#pragma unroll
        for (int k = 0; k < 64; k += 2) {
            ulonglong2 hp0 = *(const ulonglong2*)(hbase + k*4);
            ulonglong2 hp1 = *(const ulonglong2*)(hbase + (k+1)*4);
            unsigned long long wp0 = pk2(w[k],   w[k]);
            unsigned long long wp1 = pk2(w[k+1], w[k+1]);
            a01a = f2fma(wp0, hp0.x, a01a);
            a23a = f2fma(wp0, hp0.y, a23a);
            a01b = f2fma(wp1, hp1.x, a01b);
            a23b = f2fma(wp1, hp1.y, a23b);
        }
        unsigned long long a01 = add2(a01a, a01b), a23 = add2(a23a, a23b);
        if (kh == 1) *(ulonglong2*)(pad + j*4) = make_ulonglong2(a01, a23);
        __syncthreads();
        int par = s & 1;
        if (kh == 0) {
            ulonglong2 pp = *(const ulonglong2*)(pad + j*4);
            a01 = add2(a01, pp.x);
            a23 = add2(a23, pp.y);
            float g0, g1, g2, g3;
            upk2(a01, g0, g1); upk2(a23, g2, g3);
            int base = j*5;
            gl[base+0]=g0; gl[base+1]=g1; gl[base+2]=g2; gl[base+3]=g3;
            uint32_t pa = ge_peer + (uint32_t)(par*1280 + base)*4u;
            stpeer(pa, g0); stpeer(pa+4u, g1); stpeer(pa+8u, g2); stpeer(pa+12u, g3);
        }
        CLUSTER_SYNC();
        if (t+1 < TT && tid < RB*ZD) {   // gate reads of z done; safe to overwrite
            int r = tid >> 4, zi = tid & 15;
            z4[zi*4 + r] = znext;
        }
        const float* gif = rank ? (ge + par*1280) : gl;
        const float* ggo = rank ? gl : (ge + par*1280);
        {
            int r = tid >> 7, hi = tid & 127;
            float i_ = sigf(gif[hi*5+r]);
            float f_ = sigf(gif[(128+hi)*5+r]);
            float g_ = tanha(ggo[hi*5+r]);
            float o_ = sigf(ggo[(128+hi)*5+r]);
            c_ = f_*c_ + i_*g_;
            float h = o_*tanha(c_);
            h4[hi*4+r] = h;
            if (!rank) d_hdec[((size_t)(b0+r)*TT + t)*HH + hi] = h;
        }
        __syncthreads();
    }
}

// ---------------- inference loop ----------------
__global__ void __launch_bounds__(NTH,1) __cluster_dims__(2,1,1)
inference_kernel(const float* __restrict__ eps,
                 const float* __restrict__ Wm, const float* __restrict__ bm,
                 const float* __restrict__ Wv, const float* __restrict__ bv,
                 float* __restrict__ out_mean, float* __restrict__ out_logvar,
                 float* __restrict__ out_z)
{
    extern __shared__ float sm[];
    float* h4  = sm + SI_H4;
    float* pad = sm + SI_PAD;
    float* W0R = sm + SI_W0R;
    float* whd = sm + SI_WHD;
    float* hm  = sm + SI_HM;
    float* gl  = sm + SI_GL;
    float* ge  = sm + SI_GE;
    float* mv  = sm + SI_MV;
    float* z4  = sm + SI_Z4;
    int tid = threadIdx.x;
    int j   = tid & 255;
    int kh  = tid >> 8;
    uint32_t rank = blockIdx.x & 1u;
    int b0 = (blockIdx.x >> 1) * RB;
    int col = rank*256 + j;

    float w[64];
#pragma unroll
    for (int k = 0; k < 64; k++) w[k] = d_WTgz[(kh*64 + k)*GG + col];
    float wz[ZD];
#pragma unroll
    for (int k = 0; k < ZD; k++) wz[k] = d_WihTgz[k*GG + col];
    float bg = d_bgz[col];

    for (int i = tid; i < HH*HH; i += NTH) W0R[i] = d_W0RT[i];
    for (int i = tid; i < 32*HH; i += NTH) {
        int row = i >> 7, k = i & 127;
        whd[row*132 + k] = (row < 16) ? Wm[row*HH + k] : Wv[(row-16)*HH + k];
    }
    // heads role: 64 outputs x 8-way k-split
    int outv = tid >> 3, kq = tid & 7;
    int rr_h = (outv >> 5) & 1, head = (outv >> 4) & 1, zi_h = outv & 15;
    float hbias = head ? bv[zi_h] : bm[zi_h];
    // MLP role: out = tid&255 -> (row rrm, col jm), kh = k-half
    int jm = tid & 127, rrm = (tid >> 7) & 1;
    int browm = b0 + rank*2 + rrm;
    int hidxm = rank*2 + rrm;
    // reparam role
    int rr_z = (tid >> 4) & 1, zi_z = tid & 15;
    int brow_z = b0 + rank*2 + rr_z;

    for (int i = tid; i < 512; i += NTH) h4[i] = 0.f;
    float c_ = 0.f;
    __syncthreads();
    CLUSTER_SYNC();
    uint32_t ge_peer = mapa_u32(s2u(ge), rank ^ 1u);
    uint32_t z4_peer = mapa_u32(s2u(z4), rank ^ 1u);

    // prefetches for t=0 (kh==0 threads own MLP input; tid<32 own eps)
    float u0pf = 0.f, epf = 0.f;
    if (kh == 0) u0pf = d_u0[((size_t)0*BB + browm)*HH + jm];
    if (tid < 32) epf = eps[((size_t)0*BB + brow_z)*ZD + zi_z];

    uint32_t s = 0;
    for (int t = 0; t < TT; ++t, ++s) {
        float u0c = u0pf;
        float ec = epf;
        if (t+1 < TT) {
            if (kh == 0) u0pf = d_u0[((size_t)(t+1)*BB + browm)*HH + jm];
            if (tid < 32) epf = eps[((size_t)(t+1)*BB + brow_z)*ZD + zi_z];
        }
        // 1) MLP partial: out (rrm,jm), k-half kh
        {
            float aa = (kh == 0) ? u0c : 0.f, ab = 0.f;
            const float* wb = W0R + kh*64*HH;
            const float* hb = h4 + kh*256;
#pragma unroll
            for (int k = 0; k < 64; k += 2) {
                aa += wb[k*HH + jm]     * hb[k*4 + hidxm];
                ab += wb[(k+1)*HH + jm] * hb[(k+1)*4 + hidxm];
            }
            float acc = aa + ab;
            if (kh == 1) pad[(rrm*128 + jm)] = acc;
            __syncthreads();
            if (kh == 0) {
                acc += pad[rrm*128 + jm];
                hm[rrm*HH + jm] = tanha(acc);
            }
        }
        __syncthreads();
        // 2) heads: 64 outputs x 8-way k-split
        {
            const float* wrow = whd + (head*16 + zi_h)*132 + kq*16;
            const float* hr   = hm + rr_h*HH + kq*16;
            float s0=0.f, s1=0.f, s2=0.f, s3=0.f;
#pragma unroll
            for (int kk = 0; kk < 16; kk += 4) {
                float4 wv4 = *(const float4*)(wrow + kk);
                float4 hv4 = *(const float4*)(hr + kk);
                s0 += wv4.x*hv4.x; s1 += wv4.y*hv4.y;
                s2 += wv4.z*hv4.z; s3 += wv4.w*hv4.w;
            }
            float acc = (s0+s1) + (s2+s3);
            acc += __shfl_xor_sync(0xffffffffu, acc, 1);
            acc += __shfl_xor_sync(0xffffffffu, acc, 2);
            acc += __shfl_xor_sync(0xffffffffu, acc, 4);
            if (kq == 0) mv[outv] = acc + hbias;
        }
        __syncthreads();
        // 3) reparameterize own 2 rows, exchange z
        if (tid < 32) {
            float mn = mv[rr_z*32 + zi_z];
            float lv = mv[rr_z*32 + 16 + zi_z];
            float zv = ec*expf(0.5f*lv) + mn;
            int slot = zi_z*4 + rank*2 + rr_z;
            z4[slot] = zv;
            stpeer(z4_peer + (uint32_t)slot*4u, zv);
            size_t oidx = (size_t)brow_z*ZD*TT + (size_t)zi_z*TT + t;
            out_mean[oidx]   = mn;
            out_logvar[oidx] = lv;
            out_z[oidx]      = zv;
            d_zbuf[((size_t)brow_z*TT + t)*ZD + zi_z] = zv;
        }
        CLUSTER_SYNC();
        // 4) g_z gates: k-split
        unsigned long long a01a = 0ull, a23a = 0ull, a01b = 0ull, a23b = 0ull;
        if (kh == 0) {
            a01a = pk2(bg, bg); a23a = a01a;
#pragma unroll
            for (int k = 0; k < ZD; k += 2) {
                ulonglong2 zp0 = *(const ulonglong2*)(z4 + k*4);
                ulonglong2 zp1 = *(const ulonglong2*)(z4 + (k+1)*4);
                unsigned long long wp0 = pk2(wz[k],   wz[k]);
                unsigned long long wp1 = pk2(wz[k+1], wz[k+1]);
                a01a = f2fma(wp0, zp0.x, a01a);
                a23a = f2fma(wp0, zp0.y, a23a);
                a01b = f2fma(wp1, zp1.x, a01b);
                a23b = f2fma(wp1, zp1.y, a23b);
            }
        }
        const float* hbase = h4 + kh*256;
#pragma unroll
        for (int k = 0; k < 64; k += 2) {
            ulonglong2 hp0 = *(const ulonglong2*)(hbase + k*4);
            ulonglong2 hp1 = *(const ulonglong2*)(hbase + (k+1)*4);
            unsigned long long wp0 = pk2(w[k],   w[k]);
            unsigned long long wp1 = pk2(w[k+1], w[k+1]);
            a01a = f2fma(wp0, hp0.x, a01a);
            a23a = f2fma(wp0, hp0.y, a23a);
            a01b = f2fma(wp1, hp1.x, a01b);
            a23b = f2fma(wp1, hp1.y, a23b);
        }
        unsigned long long a01 = add2(a01a, a01b), a23 = add2(a23a, a23b);
        if (kh == 1) *(ulonglong2*)(pad + j*4) = make_ulonglong2(a01, a23);
        __syncthreads();
        int par = s & 1;
        if (kh == 0) {
            ulonglong2 pp = *(const ulonglong2*)(pad + j*4);
            a01 = add2(a01, pp.x);
            a23 = add2(a23, pp.y);
            float g0, g1, g2, g3;
            upk2(a01, g0, g1); upk2(a23, g2, g3);
            int base = j*5;
            gl[base+0]=g0; gl[base+1]=g1; gl[base+2]=g2; gl[base+3]=g3;
            uint32_t pa = ge_peer + (uint32_t)(par*1280 + base)*4u;
            stpeer(pa, g0); stpeer(pa+4u, g1); stpeer(pa+8u, g2); stpeer(pa+12u, g3);
        }
        CLUSTER_SYNC();
        const float* gif = rank ? (ge + par*1280) : gl;
        const float* ggo = rank ? gl : (ge + par*1280);
        {
            int r = tid >> 7, hi = tid & 127;
            float i_ = sigf(gif[hi*5+r]);
            float f_ = sigf(gif[(128+hi)*5+r]);
            float g_ = tanha(ggo[hi*5+r]);
            float o_ = sigf(ggo[(128+hi)*5+r]);
            c_ = f_*c_ + i_*g_;
            h4[hi*4+r] = o_*tanha(c_);
        }
        __syncthreads();
    }
}

// ---------------- host launcher ----------------
extern "C" void kernel_launch(void* const* d_in, const int* in_sizes, int n_in,
                              void* d_out, int out_size)
{
    (void)in_sizes; (void)n_in; (void)out_size;
    const float* x      = (const float*)d_in[0];
    const float* eps    = (const float*)d_in[1];
    const float* Wih_gx = (const float*)d_in[2];
    const float* Whh_gx = (const float*)d_in[3];
    const float* bih_gx = (const float*)d_in[4];
    const float* bhh_gx = (const float*)d_in[5];
    const float* Wih_gz = (const float*)d_in[6];
    const float* Whh_gz = (const float*)d_in[7];
    const float* bih_gz = (const float*)d_in[8];
    const float* bhh_gz = (const float*)d_in[9];
    const float* W0     = (const float*)d_in[10];
    const float* b0     = (const float*)d_in[11];
    const float* Wm     = (const float*)d_in[12];
    const float* bm     = (const float*)d_in[13];
    const float* Wv     = (const float*)d_in[14];
    const float* bv     = (const float*)d_in[15];
    const float* Wih_h  = (const float*)d_in[16];
    const float* Whh_h  = (const float*)d_in[17];
    const float* bih_h  = (const float*)d_in[18];
    const float* bhh_h  = (const float*)d_in[19];
    const float* Wy     = (const float*)d_in[20];
    const float* by     = (const float*)d_in[21];

    float *p_xT, *p_gates, *p_gx, *p_u0, *p_hdec, *p_bgx;
    cudaGetSymbolAddress((void**)&p_xT,    d_xT);
    cudaGetSymbolAddress((void**)&p_gates, d_gates);
    cudaGetSymbolAddress((void**)&p_gx,    d_gx);
    cudaGetSymbolAddress((void**)&p_u0,    d_u0);
    cudaGetSymbolAddress((void**)&p_hdec,  d_hdec);
    cudaGetSymbolAddress((void**)&p_bgx,   d_bgx);

    cudaFuncSetAttribute(lstm_gx_kernel,   cudaFuncAttributeMaxDynamicSharedMemorySize, SMB_LSTM);
    cudaFuncSetAttribute(lstm_dec_kernel,  cudaFuncAttributeMaxDynamicSharedMemorySize, SMB_LSTM);
    cudaFuncSetAttribute(inference_kernel, cudaFuncAttributeMaxDynamicSharedMemorySize, SMB_INF);

    float* out = (float*)d_out;
    const size_t Y_SZ  = (size_t)BB*XD*TT;
    const size_t MV_SZ = (size_t)BB*ZD*TT;

    prep_weights<<<64, 256>>>(Whh_gx, bih_gx, bhh_gx, Wih_gz, Whh_gz, bih_gz, bhh_gz,
                              W0, Wih_h, Whh_h, bih_h, bhh_h);
    transpose_x<<<dim3(XROWS/32, TT/32), 256>>>(x);

    // A) input gates -> [t][gate][256b] layout
    gemm_tn<2><<<dim3(TT*BB/128, GG/64), 256>>>(p_xT, XD, Wih_gx, XD, p_bgx, p_gates,
                                                TT*BB, GG, XD);
    // B) backward LSTM -> gx
    lstm_gx_kernel<<<2*NCLUST, NTH, SMB_LSTM>>>();
    // B2) u0 = gx @ W0_left^T + b0  (row-major (t,b,128))
    gemm_tn<0><<<dim3(TT*BB/128, HH/64), 256>>>(p_gx, HH, W0, 2*HH, b0, p_u0,
                                                TT*BB, HH, HH);
    // C) inference loop
    inference_kernel<<<2*NCLUST, NTH, SMB_INF>>>(eps, Wm, bm, Wv, bv,
                                                 out + Y_SZ, out + Y_SZ + MV_SZ,
                                                 out + Y_SZ + 2*MV_SZ);
    // E) decoder LSTM -> hdec
    lstm_dec_kernel<<<2*NCLUST, NTH, SMB_LSTM>>>();
    // F) y = exp(hdec @ Wy^T + by) -> (B,257,T)
    gemm_tn<1><<<dim3(TT*BB/128, (XD+63)/64), 256>>>(p_hdec, HH, Wy, HH, by, out,
                                                     TT*BB, XD, HH);
}